// round 3
// baseline (speedup 1.0000x reference)
#include <cuda_runtime.h>
#include <cstdint>
#include <cstddef>

#define N_NODES 50000
#define N_EDGES 800000
#define D_IN 128
#define D_HID 256
#define D_OUT 128

// ---- device scratch (no allocations allowed) ----
__device__ __align__(16) float g_msg1[(size_t)N_NODES * D_IN];   // layer1 message sums
__device__ __align__(16) float g_msg2[(size_t)N_NODES * D_HID];  // layer2 message sums
__device__ __align__(16) float g_h[(size_t)N_NODES * D_HID];     // hidden activations
__device__ __align__(16) float g_deg[N_NODES];
__device__ __align__(16) float g_dinv[N_NODES];
__device__ __align__(16) int   g_eidx[2 * N_EDGES];              // unpacked src|dst as int32
__device__ int g_fmt;                                            // 1 = int64 storage, 0 = int32

// ---------------------------------------------------------------
// detect edge_index storage format (device-side, deterministic)
// int64 little-endian with values < 2^31 -> every odd int32 word is 0
// ---------------------------------------------------------------
__global__ void detect_kernel(const int* __restrict__ ei32) {
    if (threadIdx.x == 0 && blockIdx.x == 0) {
        int odd_nonzero = 0;
        for (int i = 0; i < 512; i++) odd_nonzero += (ei32[2 * i + 1] != 0);
        g_fmt = (odd_nonzero == 0) ? 1 : 0;
    }
}

// unpack edge indices to int32 regardless of storage format
__global__ void convert_kernel(const void* __restrict__ ei) {
    int i = blockIdx.x * blockDim.x + threadIdx.x;
    if (i >= 2 * N_EDGES) return;
    int v;
    if (g_fmt) v = (int)((const long long*)ei)[i];
    else       v = ((const int*)ei)[i];
    g_eidx[i] = v;
}

// ---------------------------------------------------------------
// zero the accumulators (every replay; graph-captured)
// ---------------------------------------------------------------
__global__ void init_kernel() {
    size_t i = (size_t)blockIdx.x * blockDim.x + threadIdx.x;
    size_t stride = (size_t)gridDim.x * blockDim.x;
    const float4 z = make_float4(0.f, 0.f, 0.f, 0.f);
    size_t n1 = (size_t)N_NODES * D_IN / 4;
    for (size_t v = i; v < n1; v += stride) ((float4*)g_msg1)[v] = z;
    size_t n2 = (size_t)N_NODES * D_HID / 4;
    for (size_t v = i; v < n2; v += stride) ((float4*)g_msg2)[v] = z;
    for (size_t v = i; v < N_NODES; v += stride) g_deg[v] = 0.f;
}

// ---------------------------------------------------------------
// in-degree (count of edges per dst), then inverse
// ---------------------------------------------------------------
__global__ void deg_kernel() {
    int e = blockIdx.x * blockDim.x + threadIdx.x;
    if (e < N_EDGES) atomicAdd(&g_deg[g_eidx[N_EDGES + e]], 1.0f);
}

__global__ void dinv_kernel() {
    int i = blockIdx.x * blockDim.x + threadIdx.x;
    if (i < N_NODES) g_dinv[i] = 1.0f / fmaxf(g_deg[i], 1.0f);
}

// ---------------------------------------------------------------
// scatter: out[dst] += feat[src], one warp per edge, vector red
// ---------------------------------------------------------------
template <int D>
__global__ void scatter_kernel(const float* __restrict__ feat,
                               float* __restrict__ out) {
    int warp = (blockIdx.x * blockDim.x + threadIdx.x) >> 5;
    int lane = threadIdx.x & 31;
    if (warp >= N_EDGES) return;
    int s = g_eidx[warp];
    int d = g_eidx[N_EDGES + warp];
    const float4* fs = (const float4*)(feat + (size_t)s * D);
    float* od = out + (size_t)d * D;
#pragma unroll
    for (int c = lane; c < D / 4; c += 32) {
        float4 v = __ldg(&fs[c]);
        asm volatile(
            "red.global.add.v4.f32 [%0], {%1, %2, %3, %4};"
            :: "l"(od + c * 4), "f"(v.x), "f"(v.y), "f"(v.z), "f"(v.w)
            : "memory");
    }
}

// ---------------------------------------------------------------
// fused concat-K GEMM: C[M,N] = (A1*dscale)@W1^T + A2@W2^T + bias (opt ReLU)
// A1:[M,K1] A2:[M,K2] W1:[N,K1] W2:[N,K2], BM=BN=128, BK=16,
// 256 threads, 8x8 per-thread tile using packed fma.rn.f32x2.
// ---------------------------------------------------------------
__global__ void __launch_bounds__(256, 2) gemm_cat_kernel(
    const float* __restrict__ A1, int K1,
    const float* __restrict__ A2, int K2,
    const float* __restrict__ W1, const float* __restrict__ W2,
    const float* __restrict__ bias, const float* __restrict__ dscale,
    float* __restrict__ C, int M, int N, int doRelu) {
    constexpr int BM = 128, BN = 128, BK = 16;
    __shared__ float As[BK][BM];
    __shared__ float Bs[BK][BN];

    int tid = threadIdx.x;
    int m0 = blockIdx.y * BM;
    int n0 = blockIdx.x * BN;
    int tx = tid & 15, ty = tid >> 4;
    int tm = ty * 8, tn = tx * 8;

    unsigned long long acc[8][4];
#pragma unroll
    for (int i = 0; i < 8; i++)
#pragma unroll
        for (int j = 0; j < 4; j++) acc[i][j] = 0ULL;

    int K = K1 + K2;
    for (int k0 = 0; k0 < K; k0 += BK) {
        bool first = (k0 < K1);
        const float* A = first ? A1 : A2;
        const float* W = first ? W1 : W2;
        int ld = first ? K1 : K2;
        int kk = first ? k0 : (k0 - K1);

#pragma unroll
        for (int i = 0; i < 2; i++) {
            int v = tid * 2 + i;       // 0..511
            int row = v >> 2;
            int cq = v & 3;
            int gm = m0 + row;
            float4 a4 = make_float4(0.f, 0.f, 0.f, 0.f);
            if (gm < M) {
                a4 = __ldg((const float4*)(A + (size_t)gm * ld + kk) + cq);
                if (first) {
                    float s = dscale[gm];
                    a4.x *= s; a4.y *= s; a4.z *= s; a4.w *= s;
                }
            }
            As[cq * 4 + 0][row] = a4.x;
            As[cq * 4 + 1][row] = a4.y;
            As[cq * 4 + 2][row] = a4.z;
            As[cq * 4 + 3][row] = a4.w;

            int n = v >> 2;
            int kq = v & 3;
            float4 w4 = __ldg((const float4*)(W + (size_t)(n0 + n) * ld + kk) + kq);
            Bs[kq * 4 + 0][n] = w4.x;
            Bs[kq * 4 + 1][n] = w4.y;
            Bs[kq * 4 + 2][n] = w4.z;
            Bs[kq * 4 + 3][n] = w4.w;
        }
        __syncthreads();

#pragma unroll
        for (int k = 0; k < BK; k++) {
            float4 a0 = *(const float4*)&As[k][tm];
            float4 a1 = *(const float4*)&As[k][tm + 4];
            ulonglong2 b0 = *(const ulonglong2*)&Bs[k][tn];
            ulonglong2 b1 = *(const ulonglong2*)&Bs[k][tn + 4];
            unsigned long long bp0 = b0.x, bp1 = b0.y, bp2 = b1.x, bp3 = b1.y;
            float av[8] = {a0.x, a0.y, a0.z, a0.w, a1.x, a1.y, a1.z, a1.w};
#pragma unroll
            for (int i = 0; i < 8; i++) {
                unsigned long long ap;
                asm("mov.b64 %0, {%1, %1};" : "=l"(ap) : "f"(av[i]));
                asm("fma.rn.f32x2 %0, %1, %2, %0;" : "+l"(acc[i][0]) : "l"(ap), "l"(bp0));
                asm("fma.rn.f32x2 %0, %1, %2, %0;" : "+l"(acc[i][1]) : "l"(ap), "l"(bp1));
                asm("fma.rn.f32x2 %0, %1, %2, %0;" : "+l"(acc[i][2]) : "l"(ap), "l"(bp2));
                asm("fma.rn.f32x2 %0, %1, %2, %0;" : "+l"(acc[i][3]) : "l"(ap), "l"(bp3));
            }
        }
        __syncthreads();
    }

#pragma unroll
    for (int i = 0; i < 8; i++) {
        int gm = m0 + tm + i;
        if (gm >= M) break;
        float outv[8];
#pragma unroll
        for (int j = 0; j < 4; j++) {
            float lo, hi;
            asm("mov.b64 {%0, %1}, %2;" : "=f"(lo), "=f"(hi) : "l"(acc[i][j]));
            outv[2 * j] = lo;
            outv[2 * j + 1] = hi;
        }
#pragma unroll
        for (int j = 0; j < 8; j++) {
            float c = outv[j] + __ldg(&bias[n0 + tn + j]);
            if (doRelu) c = fmaxf(c, 0.0f);
            outv[j] = c;
        }
        *(float4*)(C + (size_t)gm * N + n0 + tn) =
            make_float4(outv[0], outv[1], outv[2], outv[3]);
        *(float4*)(C + (size_t)gm * N + n0 + tn + 4) =
            make_float4(outv[4], outv[5], outv[6], outv[7]);
    }
}

// ---------------------------------------------------------------
// launch
// inputs: x, Wl1, bl1, Wr1, Wl2, bl2, Wr2, edge_index
// ---------------------------------------------------------------
extern "C" void kernel_launch(void* const* d_in, const int* in_sizes, int n_in,
                              void* d_out, int out_size) {
    const float* x   = (const float*)d_in[0];
    const float* Wl1 = (const float*)d_in[1];
    const float* bl1 = (const float*)d_in[2];
    const float* Wr1 = (const float*)d_in[3];
    const float* Wl2 = (const float*)d_in[4];
    const float* bl2 = (const float*)d_in[5];
    const float* Wr2 = (const float*)d_in[6];
    const void*  ei  = d_in[7];
    float* out = (float*)d_out;

    float *msg1, *msg2, *h, *dinv;
    cudaGetSymbolAddress((void**)&msg1, g_msg1);
    cudaGetSymbolAddress((void**)&msg2, g_msg2);
    cudaGetSymbolAddress((void**)&h, g_h);
    cudaGetSymbolAddress((void**)&dinv, g_dinv);

    const int M = N_NODES;

    // 0. decode edge_index (robust to int32 or int64 storage)
    detect_kernel<<<1, 32>>>((const int*)ei);
    convert_kernel<<<(2 * N_EDGES + 255) / 256, 256>>>(ei);

    // 1. zero accumulators + degree
    init_kernel<<<1024, 256>>>();

    // 2. degree + inverse
    deg_kernel<<<(N_EDGES + 255) / 256, 256>>>();
    dinv_kernel<<<(N_NODES + 255) / 256, 256>>>();

    // 3. layer 1 scatter: msg1[dst] += x[src]
    scatter_kernel<D_IN><<<(N_EDGES + 7) / 8, 256>>>(x, msg1);

    // 4. layer 1 GEMM: h = relu(mean1@Wl1^T + bl1 + x@Wr1^T)
    {
        dim3 grid(D_HID / 128, (M + 127) / 128);
        gemm_cat_kernel<<<grid, 256>>>(msg1, D_IN, x, D_IN, Wl1, Wr1, bl1,
                                       dinv, h, M, D_HID, 1);
    }

    // 5. layer 2 scatter: msg2[dst] += h[src]
    scatter_kernel<D_HID><<<(N_EDGES + 7) / 8, 256>>>(h, msg2);

    // 6. layer 2 GEMM: out = mean2@Wl2^T + bl2 + h@Wr2^T
    {
        dim3 grid(D_OUT / 128, (M + 127) / 128);
        gemm_cat_kernel<<<grid, 256>>>(msg2, D_HID, h, D_HID, Wl2, Wr2, bl2,
                                       dinv, out, M, D_OUT, 0);
    }
}

// round 4
// speedup vs baseline: 1.1573x; 1.1573x over previous
#include <cuda_runtime.h>
#include <cstdint>
#include <cstddef>

#define N_NODES 50000
#define N_EDGES 800000
#define D_IN 128
#define D_HID 256
#define D_OUT 128

// ---- device scratch (no allocations allowed) ----
__device__ __align__(16) float g_msg1[(size_t)N_NODES * D_IN];   // layer1 msg sums / reused as p
__device__ __align__(16) float g_buf2[(size_t)N_NODES * D_HID];  // q | msg2g (two 128-wide halves)
__device__ __align__(16) float g_h[(size_t)N_NODES * D_HID];     // hidden activations
__device__ __align__(16) float g_dinv[N_NODES];
__device__ __align__(16) int   g_eidx[2 * N_EDGES];              // unpacked src|dst int32
__device__ __align__(16) int   g_degi[N_NODES];
__device__ __align__(16) int   g_row[N_NODES + 1];               // CSR row starts (by dst)
__device__ __align__(16) int   g_cur[N_NODES];                   // fill cursors
__device__ __align__(16) int   g_csrc[N_EDGES];                  // src ids grouped by dst
__device__ int g_fmt;                                            // 1 = int64 storage, 0 = int32

// ---------------------------------------------------------------
// detect edge_index storage format (int64 little-endian < 2^31 ->
// every odd int32 word is 0)
// ---------------------------------------------------------------
__global__ void detect_kernel(const int* __restrict__ ei32) {
    if (threadIdx.x == 0 && blockIdx.x == 0) {
        int odd_nonzero = 0;
        for (int i = 0; i < 512; i++) odd_nonzero += (ei32[2 * i + 1] != 0);
        g_fmt = (odd_nonzero == 0) ? 1 : 0;
    }
}

__global__ void zero_deg_kernel() {
    int i = blockIdx.x * blockDim.x + threadIdx.x;
    if (i < N_NODES) g_degi[i] = 0;
}

// unpack edge indices to int32 and count in-degrees (dst half)
__global__ void convert_kernel(const void* __restrict__ ei) {
    int i = blockIdx.x * blockDim.x + threadIdx.x;
    if (i >= 2 * N_EDGES) return;
    int v;
    if (g_fmt) v = (int)((const long long*)ei)[i];
    else       v = ((const int*)ei)[i];
    g_eidx[i] = v;
    if (i >= N_EDGES) atomicAdd(&g_degi[v], 1);
}

// ---------------------------------------------------------------
// single-block exclusive scan of g_degi -> g_row  (50001 entries)
// ---------------------------------------------------------------
__global__ void scan_kernel() {
    __shared__ int sums[1024];
    const int CH = (N_NODES + 1023) / 1024;  // 49
    int t = threadIdx.x;
    int begin = t * CH;
    int end = begin + CH; if (end > N_NODES) end = N_NODES;
    if (begin > N_NODES) begin = N_NODES;
    int s = 0;
    for (int i = begin; i < end; i++) s += g_degi[i];
    sums[t] = s;
    __syncthreads();
    // Hillis-Steele inclusive scan over 1024 partials
    for (int off = 1; off < 1024; off <<= 1) {
        int v = (t >= off) ? sums[t - off] : 0;
        __syncthreads();
        sums[t] += v;
        __syncthreads();
    }
    int run = sums[t] - s;  // exclusive prefix
    for (int i = begin; i < end; i++) {
        g_row[i] = run;
        run += g_degi[i];
    }
    if (t == 1023) g_row[N_NODES] = run;
}

// dinv + copy row -> cursor
__global__ void dinv_cur_kernel() {
    int i = blockIdx.x * blockDim.x + threadIdx.x;
    if (i < N_NODES) {
        g_dinv[i] = 1.0f / fmaxf((float)g_degi[i], 1.0f);
        g_cur[i] = g_row[i];
    }
}

// group edge sources by dst
__global__ void reorder_kernel() {
    int e = blockIdx.x * blockDim.x + threadIdx.x;
    if (e >= N_EDGES) return;
    int d = g_eidx[N_EDGES + e];
    int pos = atomicAdd(&g_cur[d], 1);
    g_csrc[pos] = g_eidx[e];
}

// ---------------------------------------------------------------
// gather: out[n] = sum_{e in row[n]..row[n+1]} feat[csrc[e]]
// one warp per node, 128-wide features, float4 per lane, no atomics
// ---------------------------------------------------------------
__global__ void gather_kernel(const float* __restrict__ feat,
                              float* __restrict__ out) {
    int warp = (blockIdx.x * blockDim.x + threadIdx.x) >> 5;
    int lane = threadIdx.x & 31;
    if (warp >= N_NODES) return;
    int start = g_row[warp];
    int end = g_row[warp + 1];
    float4 acc = make_float4(0.f, 0.f, 0.f, 0.f);
    for (int base = start; base < end; base += 32) {
        int mye = base + lane;
        int sidx = (mye < end) ? g_csrc[mye] : 0;
        int cnt = end - base; if (cnt > 32) cnt = 32;
        for (int j = 0; j < cnt; j++) {
            int s = __shfl_sync(0xffffffffu, sidx, j);
            float4 v = __ldg((const float4*)(feat + (size_t)s * 128) + lane);
            acc.x += v.x; acc.y += v.y; acc.z += v.z; acc.w += v.w;
        }
    }
    ((float4*)(out + (size_t)warp * 128))[lane] = acc;
}

// ---------------------------------------------------------------
// fused concat-K GEMM: C[M,N] = (A1*scale?)@W1^T [+ A2@W2^T] + bias? (opt ReLU)
// A1:[M,K1] A2:[M,K2] W1:[N,K1] W2:[N,K2], BM=BN=128, BK=16,
// 256 threads, 8x8 per-thread tile using packed fma.rn.f32x2.
// K2 may be 0 (A2/W2 unused); dscale/bias may be null.
// ---------------------------------------------------------------
__global__ void __launch_bounds__(256, 2) gemm_cat_kernel(
    const float* __restrict__ A1, int K1,
    const float* __restrict__ A2, int K2,
    const float* __restrict__ W1, const float* __restrict__ W2,
    const float* __restrict__ bias, const float* __restrict__ dscale,
    float* __restrict__ C, int M, int N, int doRelu) {
    constexpr int BM = 128, BN = 128, BK = 16;
    __shared__ float As[BK][BM];
    __shared__ float Bs[BK][BN];

    int tid = threadIdx.x;
    int m0 = blockIdx.y * BM;
    int n0 = blockIdx.x * BN;
    int tx = tid & 15, ty = tid >> 4;
    int tm = ty * 8, tn = tx * 8;

    unsigned long long acc[8][4];
#pragma unroll
    for (int i = 0; i < 8; i++)
#pragma unroll
        for (int j = 0; j < 4; j++) acc[i][j] = 0ULL;

    int K = K1 + K2;
    for (int k0 = 0; k0 < K; k0 += BK) {
        bool first = (k0 < K1);
        const float* A = first ? A1 : A2;
        const float* W = first ? W1 : W2;
        int ld = first ? K1 : K2;
        int kk = first ? k0 : (k0 - K1);

#pragma unroll
        for (int i = 0; i < 2; i++) {
            int v = tid * 2 + i;       // 0..511
            int row = v >> 2;
            int cq = v & 3;
            int gm = m0 + row;
            float4 a4 = make_float4(0.f, 0.f, 0.f, 0.f);
            if (gm < M) {
                a4 = __ldg((const float4*)(A + (size_t)gm * ld + kk) + cq);
                if (first && dscale) {
                    float s = dscale[gm];
                    a4.x *= s; a4.y *= s; a4.z *= s; a4.w *= s;
                }
            }
            As[cq * 4 + 0][row] = a4.x;
            As[cq * 4 + 1][row] = a4.y;
            As[cq * 4 + 2][row] = a4.z;
            As[cq * 4 + 3][row] = a4.w;

            int n = v >> 2;
            int kq = v & 3;
            float4 w4 = __ldg((const float4*)(W + (size_t)(n0 + n) * ld + kk) + kq);
            Bs[kq * 4 + 0][n] = w4.x;
            Bs[kq * 4 + 1][n] = w4.y;
            Bs[kq * 4 + 2][n] = w4.z;
            Bs[kq * 4 + 3][n] = w4.w;
        }
        __syncthreads();

#pragma unroll
        for (int k = 0; k < BK; k++) {
            float4 a0 = *(const float4*)&As[k][tm];
            float4 a1 = *(const float4*)&As[k][tm + 4];
            ulonglong2 b0 = *(const ulonglong2*)&Bs[k][tn];
            ulonglong2 b1 = *(const ulonglong2*)&Bs[k][tn + 4];
            unsigned long long bp0 = b0.x, bp1 = b0.y, bp2 = b1.x, bp3 = b1.y;
            float av[8] = {a0.x, a0.y, a0.z, a0.w, a1.x, a1.y, a1.z, a1.w};
#pragma unroll
            for (int i = 0; i < 8; i++) {
                unsigned long long ap;
                asm("mov.b64 %0, {%1, %1};" : "=l"(ap) : "f"(av[i]));
                asm("fma.rn.f32x2 %0, %1, %2, %0;" : "+l"(acc[i][0]) : "l"(ap), "l"(bp0));
                asm("fma.rn.f32x2 %0, %1, %2, %0;" : "+l"(acc[i][1]) : "l"(ap), "l"(bp1));
                asm("fma.rn.f32x2 %0, %1, %2, %0;" : "+l"(acc[i][2]) : "l"(ap), "l"(bp2));
                asm("fma.rn.f32x2 %0, %1, %2, %0;" : "+l"(acc[i][3]) : "l"(ap), "l"(bp3));
            }
        }
        __syncthreads();
    }

#pragma unroll
    for (int i = 0; i < 8; i++) {
        int gm = m0 + tm + i;
        if (gm >= M) break;
        float outv[8];
#pragma unroll
        for (int j = 0; j < 4; j++) {
            float lo, hi;
            asm("mov.b64 {%0, %1}, %2;" : "=f"(lo), "=f"(hi) : "l"(acc[i][j]));
            outv[2 * j] = lo;
            outv[2 * j + 1] = hi;
        }
#pragma unroll
        for (int j = 0; j < 8; j++) {
            float c = outv[j] + (bias ? __ldg(&bias[n0 + tn + j]) : 0.0f);
            if (doRelu) c = fmaxf(c, 0.0f);
            outv[j] = c;
        }
        *(float4*)(C + (size_t)gm * N + n0 + tn) =
            make_float4(outv[0], outv[1], outv[2], outv[3]);
        *(float4*)(C + (size_t)gm * N + n0 + tn + 4) =
            make_float4(outv[4], outv[5], outv[6], outv[7]);
    }
}

// ---------------------------------------------------------------
// final: out = msg2g * dinv[node] + q    (all [N_NODES,128])
// ---------------------------------------------------------------
__global__ void final_kernel(const float* __restrict__ msg2g,
                             const float* __restrict__ q,
                             float* __restrict__ out) {
    int i4 = blockIdx.x * blockDim.x + threadIdx.x;        // float4 index
    if (i4 >= N_NODES * (D_OUT / 4)) return;
    int node = i4 >> 5;                                    // /32 float4 per row
    float s = g_dinv[node];
    float4 m = ((const float4*)msg2g)[i4];
    float4 qq = ((const float4*)q)[i4];
    float4 o;
    o.x = m.x * s + qq.x;
    o.y = m.y * s + qq.y;
    o.z = m.z * s + qq.z;
    o.w = m.w * s + qq.w;
    ((float4*)out)[i4] = o;
}

// ---------------------------------------------------------------
// launch — inputs: x, Wl1, bl1, Wr1, Wl2, bl2, Wr2, edge_index
// ---------------------------------------------------------------
extern "C" void kernel_launch(void* const* d_in, const int* in_sizes, int n_in,
                              void* d_out, int out_size) {
    const float* x   = (const float*)d_in[0];
    const float* Wl1 = (const float*)d_in[1];
    const float* bl1 = (const float*)d_in[2];
    const float* Wr1 = (const float*)d_in[3];
    const float* Wl2 = (const float*)d_in[4];
    const float* bl2 = (const float*)d_in[5];
    const float* Wr2 = (const float*)d_in[6];
    const void*  ei  = d_in[7];
    float* out = (float*)d_out;

    float *msg1, *buf2, *h, *dinv;
    cudaGetSymbolAddress((void**)&msg1, g_msg1);
    cudaGetSymbolAddress((void**)&buf2, g_buf2);
    cudaGetSymbolAddress((void**)&h, g_h);
    cudaGetSymbolAddress((void**)&dinv, g_dinv);

    float* q     = buf2;                               // [N,128]
    float* msg2g = buf2 + (size_t)N_NODES * D_OUT;     // [N,128]
    float* p     = msg1;                               // reuse after gemm1 consumes msg1

    const int M = N_NODES;

    // 0. decode edge_index + degree count
    detect_kernel<<<1, 32>>>((const int*)ei);
    zero_deg_kernel<<<(N_NODES + 255) / 256, 256>>>();
    convert_kernel<<<(2 * N_EDGES + 255) / 256, 256>>>(ei);

    // 1. CSR build: scan, dinv+cursor, reorder
    scan_kernel<<<1, 1024>>>();
    dinv_cur_kernel<<<(N_NODES + 255) / 256, 256>>>();
    reorder_kernel<<<(N_EDGES + 255) / 256, 256>>>();

    // 2. layer 1 gather: msg1[n] = sum x[neighbors]
    gather_kernel<<<(N_NODES + 7) / 8, 256>>>(x, msg1);

    // 3. layer 1 GEMM: h = relu((msg1*dinv)@Wl1^T + bl1 + x@Wr1^T)
    {
        dim3 grid(D_HID / 128, (M + 127) / 128);
        gemm_cat_kernel<<<grid, 256>>>(msg1, D_IN, x, D_IN, Wl1, Wr1, bl1,
                                       dinv, h, M, D_HID, 1);
    }

    // 4. transform-first: p = h@Wl2^T  (no scale, no bias)
    {
        dim3 grid(1, (M + 127) / 128);
        gemm_cat_kernel<<<grid, 256>>>(h, D_HID, nullptr, 0, Wl2, nullptr,
                                       nullptr, nullptr, p, M, D_OUT, 0);
    }

    // 5. layer 2 gather in output space: msg2g[n] = sum p[neighbors]
    gather_kernel<<<(N_NODES + 7) / 8, 256>>>(p, msg2g);

    // 6. q = h@Wr2^T + bl2
    {
        dim3 grid(1, (M + 127) / 128);
        gemm_cat_kernel<<<grid, 256>>>(h, D_HID, nullptr, 0, Wr2, nullptr,
                                       bl2, nullptr, q, M, D_OUT, 0);
    }

    // 7. out = msg2g*dinv + q
    final_kernel<<<(N_NODES * (D_OUT / 4) + 255) / 256, 256>>>(msg2g, q, out);
}

// round 5
// speedup vs baseline: 1.3069x; 1.1293x over previous
#include <cuda_runtime.h>
#include <cstdint>
#include <cstddef>

#define N_NODES 50000
#define N_EDGES 800000
#define D_IN 128
#define D_HID 256
#define D_OUT 128
#define SCAN_NB ((N_NODES + 255) / 256)   // 196 blocks

// ---- device scratch (no allocations allowed) ----
__device__ __align__(16) float g_msg1[(size_t)N_NODES * D_IN];   // layer1 msg sums / reused as p
__device__ __align__(16) float g_buf2[(size_t)N_NODES * D_HID];  // q | msg2g (two 128-wide halves)
__device__ __align__(16) float g_h[(size_t)N_NODES * D_HID];     // hidden activations
__device__ __align__(16) float g_dinv[N_NODES];
__device__ __align__(16) int   g_eidx[2 * N_EDGES];              // unpacked src|dst int32
__device__ __align__(16) int   g_degi[N_NODES];
__device__ __align__(16) int   g_row[N_NODES + 1];               // CSR row starts (by dst)
__device__ __align__(16) int   g_cur[N_NODES];                   // fill cursors
__device__ __align__(16) int   g_csrc[N_EDGES];                  // src ids grouped by dst
__device__ __align__(16) int   g_bsum[SCAN_NB];
__device__ __align__(16) int   g_boff[256];
__device__ int g_fmt;                                            // 1 = int64 storage, 0 = int32

// ---------------------------------------------------------------
// detect edge_index storage format (int64 little-endian < 2^31 ->
// every odd int32 word is 0)
// ---------------------------------------------------------------
__global__ void detect_kernel(const int* __restrict__ ei32) {
    if (threadIdx.x == 0 && blockIdx.x == 0) {
        int odd_nonzero = 0;
        for (int i = 0; i < 512; i++) odd_nonzero += (ei32[2 * i + 1] != 0);
        g_fmt = (odd_nonzero == 0) ? 1 : 0;
    }
}

__global__ void zero_deg_kernel() {
    int i = blockIdx.x * blockDim.x + threadIdx.x;
    if (i < N_NODES) g_degi[i] = 0;
}

// unpack edge indices to int32 and count in-degrees (dst half)
__global__ void convert_kernel(const void* __restrict__ ei) {
    int i = blockIdx.x * blockDim.x + threadIdx.x;
    if (i >= 2 * N_EDGES) return;
    int v;
    if (g_fmt) v = (int)((const long long*)ei)[i];
    else       v = ((const int*)ei)[i];
    g_eidx[i] = v;
    if (i >= N_EDGES) atomicAdd(&g_degi[v], 1);
}

// ---------------------------------------------------------------
// 3-pass multi-block exclusive scan of g_degi -> g_row
// ---------------------------------------------------------------
__global__ void scan_blocks_kernel() {           // grid SCAN_NB x 256
    __shared__ int s[256];
    int t = threadIdx.x;
    int i = blockIdx.x * 256 + t;
    int v = (i < N_NODES) ? g_degi[i] : 0;
    s[t] = v;
    __syncthreads();
#pragma unroll
    for (int off = 1; off < 256; off <<= 1) {
        int add = (t >= off) ? s[t - off] : 0;
        __syncthreads();
        s[t] += add;
        __syncthreads();
    }
    int incl = s[t];
    if (i < N_NODES) g_row[i] = incl - v;        // exclusive within block
    if (t == 255) g_bsum[blockIdx.x] = incl;     // block total
}

__global__ void scan_tops_kernel() {             // 1 block x 256
    __shared__ int s[256];
    int t = threadIdx.x;
    int v = (t < SCAN_NB) ? g_bsum[t] : 0;
    s[t] = v;
    __syncthreads();
#pragma unroll
    for (int off = 1; off < 256; off <<= 1) {
        int add = (t >= off) ? s[t - off] : 0;
        __syncthreads();
        s[t] += add;
        __syncthreads();
    }
    if (t < SCAN_NB) g_boff[t] = s[t] - v;       // exclusive block offsets
}

__global__ void scan_finish_kernel() {           // grid SCAN_NB x 256
    int i = blockIdx.x * 256 + threadIdx.x;
    if (i < N_NODES) {
        int r = g_row[i] + g_boff[blockIdx.x];
        g_row[i] = r;
        g_cur[i] = r;
        g_dinv[i] = 1.0f / fmaxf((float)g_degi[i], 1.0f);
    }
    if (i == 0) g_row[N_NODES] = N_EDGES;        // total is a constant
}

// group edge sources by dst
__global__ void reorder_kernel() {
    int e = blockIdx.x * blockDim.x + threadIdx.x;
    if (e >= N_EDGES) return;
    int d = g_eidx[N_EDGES + e];
    int pos = atomicAdd(&g_cur[d], 1);
    g_csrc[pos] = g_eidx[e];
}

// ---------------------------------------------------------------
// gather: out[n] = sum_{e in row[n]..row[n+1]} feat[csrc[e]]
// one warp per node, 128-wide features, float4 per lane, no atomics
// ---------------------------------------------------------------
__global__ void gather_kernel(const float* __restrict__ feat,
                              float* __restrict__ out) {
    int warp = (blockIdx.x * blockDim.x + threadIdx.x) >> 5;
    int lane = threadIdx.x & 31;
    if (warp >= N_NODES) return;
    int start = g_row[warp];
    int end = g_row[warp + 1];
    float4 acc = make_float4(0.f, 0.f, 0.f, 0.f);
    for (int base = start; base < end; base += 32) {
        int mye = base + lane;
        int sidx = (mye < end) ? g_csrc[mye] : 0;
        int cnt = end - base; if (cnt > 32) cnt = 32;
#pragma unroll 4
        for (int j = 0; j < cnt; j++) {
            int s = __shfl_sync(0xffffffffu, sidx, j);
            float4 v = __ldg((const float4*)(feat + (size_t)s * 128) + lane);
            acc.x += v.x; acc.y += v.y; acc.z += v.z; acc.w += v.w;
        }
    }
    ((float4*)(out + (size_t)warp * 128))[lane] = acc;
}

// ---------------------------------------------------------------
// fused concat-K GEMM: C[M,N] = (A1*scale?)@W1^T [+ A2@W2^T] + bias? (opt ReLU)
// A1:[M,K1] A2:[M,K2] W1:[N,K1] W2:[N,K2], BM=BN=128, BK=16,
// 256 threads, 8x8 per-thread tile using packed fma.rn.f32x2.
// K2 may be 0 (A2/W2 unused); dscale/bias may be null.
// ---------------------------------------------------------------
__global__ void __launch_bounds__(256, 2) gemm_cat_kernel(
    const float* __restrict__ A1, int K1,
    const float* __restrict__ A2, int K2,
    const float* __restrict__ W1, const float* __restrict__ W2,
    const float* __restrict__ bias, const float* __restrict__ dscale,
    float* __restrict__ C, int M, int N, int doRelu) {
    constexpr int BM = 128, BN = 128, BK = 16;
    __shared__ float As[BK][BM];
    __shared__ float Bs[BK][BN];

    int tid = threadIdx.x;
    int m0 = blockIdx.y * BM;
    int n0 = blockIdx.x * BN;
    int tx = tid & 15, ty = tid >> 4;
    int tm = ty * 8, tn = tx * 8;

    unsigned long long acc[8][4];
#pragma unroll
    for (int i = 0; i < 8; i++)
#pragma unroll
        for (int j = 0; j < 4; j++) acc[i][j] = 0ULL;

    int K = K1 + K2;
    for (int k0 = 0; k0 < K; k0 += BK) {
        bool first = (k0 < K1);
        const float* A = first ? A1 : A2;
        const float* W = first ? W1 : W2;
        int ld = first ? K1 : K2;
        int kk = first ? k0 : (k0 - K1);

#pragma unroll
        for (int i = 0; i < 2; i++) {
            int v = tid * 2 + i;       // 0..511
            int row = v >> 2;
            int cq = v & 3;
            int gm = m0 + row;
            float4 a4 = make_float4(0.f, 0.f, 0.f, 0.f);
            if (gm < M) {
                a4 = __ldg((const float4*)(A + (size_t)gm * ld + kk) + cq);
                if (first && dscale) {
                    float s = dscale[gm];
                    a4.x *= s; a4.y *= s; a4.z *= s; a4.w *= s;
                }
            }
            As[cq * 4 + 0][row] = a4.x;
            As[cq * 4 + 1][row] = a4.y;
            As[cq * 4 + 2][row] = a4.z;
            As[cq * 4 + 3][row] = a4.w;

            int n = v >> 2;
            int kq = v & 3;
            float4 w4 = __ldg((const float4*)(W + (size_t)(n0 + n) * ld + kk) + kq);
            Bs[kq * 4 + 0][n] = w4.x;
            Bs[kq * 4 + 1][n] = w4.y;
            Bs[kq * 4 + 2][n] = w4.z;
            Bs[kq * 4 + 3][n] = w4.w;
        }
        __syncthreads();

#pragma unroll
        for (int k = 0; k < BK; k++) {
            float4 a0 = *(const float4*)&As[k][tm];
            float4 a1 = *(const float4*)&As[k][tm + 4];
            ulonglong2 b0 = *(const ulonglong2*)&Bs[k][tn];
            ulonglong2 b1 = *(const ulonglong2*)&Bs[k][tn + 4];
            unsigned long long bp0 = b0.x, bp1 = b0.y, bp2 = b1.x, bp3 = b1.y;
            float av[8] = {a0.x, a0.y, a0.z, a0.w, a1.x, a1.y, a1.z, a1.w};
#pragma unroll
            for (int i = 0; i < 8; i++) {
                unsigned long long ap;
                asm("mov.b64 %0, {%1, %1};" : "=l"(ap) : "f"(av[i]));
                asm("fma.rn.f32x2 %0, %1, %2, %0;" : "+l"(acc[i][0]) : "l"(ap), "l"(bp0));
                asm("fma.rn.f32x2 %0, %1, %2, %0;" : "+l"(acc[i][1]) : "l"(ap), "l"(bp1));
                asm("fma.rn.f32x2 %0, %1, %2, %0;" : "+l"(acc[i][2]) : "l"(ap), "l"(bp2));
                asm("fma.rn.f32x2 %0, %1, %2, %0;" : "+l"(acc[i][3]) : "l"(ap), "l"(bp3));
            }
        }
        __syncthreads();
    }

#pragma unroll
    for (int i = 0; i < 8; i++) {
        int gm = m0 + tm + i;
        if (gm >= M) break;
        float outv[8];
#pragma unroll
        for (int j = 0; j < 4; j++) {
            float lo, hi;
            asm("mov.b64 {%0, %1}, %2;" : "=f"(lo), "=f"(hi) : "l"(acc[i][j]));
            outv[2 * j] = lo;
            outv[2 * j + 1] = hi;
        }
#pragma unroll
        for (int j = 0; j < 8; j++) {
            float c = outv[j] + (bias ? __ldg(&bias[n0 + tn + j]) : 0.0f);
            if (doRelu) c = fmaxf(c, 0.0f);
            outv[j] = c;
        }
        *(float4*)(C + (size_t)gm * N + n0 + tn) =
            make_float4(outv[0], outv[1], outv[2], outv[3]);
        *(float4*)(C + (size_t)gm * N + n0 + tn + 4) =
            make_float4(outv[4], outv[5], outv[6], outv[7]);
    }
}

// ---------------------------------------------------------------
// final: out = msg2g * dinv[node] + q    (all [N_NODES,128])
// ---------------------------------------------------------------
__global__ void final_kernel(const float* __restrict__ msg2g,
                             const float* __restrict__ q,
                             float* __restrict__ out) {
    int i4 = blockIdx.x * blockDim.x + threadIdx.x;        // float4 index
    if (i4 >= N_NODES * (D_OUT / 4)) return;
    int node = i4 >> 5;                                    // /32 float4 per row
    float s = g_dinv[node];
    float4 m = ((const float4*)msg2g)[i4];
    float4 qq = ((const float4*)q)[i4];
    float4 o;
    o.x = m.x * s + qq.x;
    o.y = m.y * s + qq.y;
    o.z = m.z * s + qq.z;
    o.w = m.w * s + qq.w;
    ((float4*)out)[i4] = o;
}

// ---------------------------------------------------------------
// launch — inputs: x, Wl1, bl1, Wr1, Wl2, bl2, Wr2, edge_index
// ---------------------------------------------------------------
extern "C" void kernel_launch(void* const* d_in, const int* in_sizes, int n_in,
                              void* d_out, int out_size) {
    const float* x   = (const float*)d_in[0];
    const float* Wl1 = (const float*)d_in[1];
    const float* bl1 = (const float*)d_in[2];
    const float* Wr1 = (const float*)d_in[3];
    const float* Wl2 = (const float*)d_in[4];
    const float* bl2 = (const float*)d_in[5];
    const float* Wr2 = (const float*)d_in[6];
    const void*  ei  = d_in[7];
    float* out = (float*)d_out;

    float *msg1, *buf2, *h, *dinv;
    cudaGetSymbolAddress((void**)&msg1, g_msg1);
    cudaGetSymbolAddress((void**)&buf2, g_buf2);
    cudaGetSymbolAddress((void**)&h, g_h);
    cudaGetSymbolAddress((void**)&dinv, g_dinv);

    float* q     = buf2;                               // [N,128]
    float* msg2g = buf2 + (size_t)N_NODES * D_OUT;     // [N,128]
    float* p     = msg1;                               // reuse after gemm1 consumes msg1

    const int M = N_NODES;

    // 0. decode edge_index + degree count
    detect_kernel<<<1, 32>>>((const int*)ei);
    zero_deg_kernel<<<(N_NODES + 255) / 256, 256>>>();
    convert_kernel<<<(2 * N_EDGES + 255) / 256, 256>>>(ei);

    // 1. CSR build: 3-pass scan (+dinv/cursor in pass 3), then reorder
    scan_blocks_kernel<<<SCAN_NB, 256>>>();
    scan_tops_kernel<<<1, 256>>>();
    scan_finish_kernel<<<SCAN_NB, 256>>>();
    reorder_kernel<<<(N_EDGES + 255) / 256, 256>>>();

    // 2. layer 1 gather: msg1[n] = sum x[neighbors]
    gather_kernel<<<(N_NODES + 7) / 8, 256>>>(x, msg1);

    // 3. layer 1 GEMM: h = relu((msg1*dinv)@Wl1^T + bl1 + x@Wr1^T)
    {
        dim3 grid(D_HID / 128, (M + 127) / 128);
        gemm_cat_kernel<<<grid, 256>>>(msg1, D_IN, x, D_IN, Wl1, Wr1, bl1,
                                       dinv, h, M, D_HID, 1);
    }

    // 4. transform-first: p = h@Wl2^T  (no scale, no bias)
    {
        dim3 grid(1, (M + 127) / 128);
        gemm_cat_kernel<<<grid, 256>>>(h, D_HID, nullptr, 0, Wl2, nullptr,
                                       nullptr, nullptr, p, M, D_OUT, 0);
    }

    // 5. layer 2 gather in output space: msg2g[n] = sum p[neighbors]
    gather_kernel<<<(N_NODES + 7) / 8, 256>>>(p, msg2g);

    // 6. q = h@Wr2^T + bl2
    {
        dim3 grid(1, (M + 127) / 128);
        gemm_cat_kernel<<<grid, 256>>>(h, D_HID, nullptr, 0, Wr2, nullptr,
                                       bl2, nullptr, q, M, D_OUT, 0);
    }

    // 7. out = msg2g*dinv + q
    final_kernel<<<(N_NODES * (D_OUT / 4) + 255) / 256, 256>>>(msg2g, q, out);
}

// round 7
// speedup vs baseline: 1.7461x; 1.3360x over previous
#include <cuda_runtime.h>
#include <cuda_bf16.h>
#include <cstdint>
#include <cstddef>

#define N_NODES 50000
#define N_EDGES 800000
#define D_IN 128
#define D_HID 256
#define D_OUT 128
#define SCAN_NB ((N_NODES + 255) / 256)   // 196 blocks
#define GEMM_MB ((N_NODES + 127) / 128)   // 391 CTAs in M

// ---- device scratch (no allocations allowed) ----
// A buffers: bf16 [M,256] packed as uints (row stride 128 uints)
__device__ __align__(16) unsigned g_A1hi[(size_t)N_NODES * 128];
__device__ __align__(16) unsigned g_A1lo[(size_t)N_NODES * 128];
__device__ __align__(16) unsigned g_A2hi[(size_t)N_NODES * 128];
__device__ __align__(16) unsigned g_A2lo[(size_t)N_NODES * 128];
__device__ __align__(16) float    g_out2[(size_t)N_NODES * 256];   // [p|q] fp32
__device__ __align__(16) float    g_msg2g[(size_t)N_NODES * 128];
// weights bf16 [256,256]
__device__ __align__(16) unsigned short g_W1hi[256 * 256];
__device__ __align__(16) unsigned short g_W1lo[256 * 256];
__device__ __align__(16) unsigned short g_W2hi[256 * 256];
__device__ __align__(16) unsigned short g_W2lo[256 * 256];
__device__ __align__(16) float g_b1[256];
__device__ __align__(16) float g_b2[256];
// graph
__device__ __align__(16) float g_dinv[N_NODES];
__device__ __align__(16) int   g_eidx[2 * N_EDGES];
__device__ __align__(16) int   g_degi[N_NODES];
__device__ __align__(16) int   g_row[N_NODES + 1];
__device__ __align__(16) int   g_cur[N_NODES];
__device__ __align__(16) int   g_csrc[N_EDGES];
__device__ __align__(16) int   g_bsum[SCAN_NB];
__device__ __align__(16) int   g_boff[256];
__device__ int g_fmt;

// ---------------- helpers ----------------
__device__ __forceinline__ void f2bf2(float v, unsigned short& h, unsigned short& l) {
    __nv_bfloat16 hb = __float2bfloat16(v);
    float hf = __bfloat162float(hb);
    __nv_bfloat16 lb = __float2bfloat16(v - hf);
    h = *reinterpret_cast<unsigned short*>(&hb);
    l = *reinterpret_cast<unsigned short*>(&lb);
}

// ---------------------------------------------------------------
// edge decode + CSR build
// ---------------------------------------------------------------
__global__ void detect_kernel(const int* __restrict__ ei32) {
    if (threadIdx.x == 0 && blockIdx.x == 0) {
        int odd_nonzero = 0;
        for (int i = 0; i < 512; i++) odd_nonzero += (ei32[2 * i + 1] != 0);
        g_fmt = (odd_nonzero == 0) ? 1 : 0;
    }
}

__global__ void zero_deg_kernel() {
    int i = blockIdx.x * blockDim.x + threadIdx.x;
    if (i < N_NODES) g_degi[i] = 0;
}

__global__ void convert_kernel(const void* __restrict__ ei) {
    int i = blockIdx.x * blockDim.x + threadIdx.x;
    if (i >= 2 * N_EDGES) return;
    int v;
    if (g_fmt) v = (int)((const long long*)ei)[i];
    else       v = ((const int*)ei)[i];
    g_eidx[i] = v;
    if (i >= N_EDGES) atomicAdd(&g_degi[v], 1);
}

__global__ void scan_blocks_kernel() {
    __shared__ int s[256];
    int t = threadIdx.x;
    int i = blockIdx.x * 256 + t;
    int v = (i < N_NODES) ? g_degi[i] : 0;
    s[t] = v;
    __syncthreads();
#pragma unroll
    for (int off = 1; off < 256; off <<= 1) {
        int add = (t >= off) ? s[t - off] : 0;
        __syncthreads();
        s[t] += add;
        __syncthreads();
    }
    int incl = s[t];
    if (i < N_NODES) g_row[i] = incl - v;
    if (t == 255) g_bsum[blockIdx.x] = incl;
}

__global__ void scan_tops_kernel() {
    __shared__ int s[256];
    int t = threadIdx.x;
    int v = (t < SCAN_NB) ? g_bsum[t] : 0;
    s[t] = v;
    __syncthreads();
#pragma unroll
    for (int off = 1; off < 256; off <<= 1) {
        int add = (t >= off) ? s[t - off] : 0;
        __syncthreads();
        s[t] += add;
        __syncthreads();
    }
    if (t < SCAN_NB) g_boff[t] = s[t] - v;
}

__global__ void scan_finish_kernel() {
    int i = blockIdx.x * 256 + threadIdx.x;
    if (i < N_NODES) {
        int r = g_row[i] + g_boff[blockIdx.x];
        g_row[i] = r;
        g_cur[i] = r;
        g_dinv[i] = 1.0f / fmaxf((float)g_degi[i], 1.0f);
    }
    if (i == 0) g_row[N_NODES] = N_EDGES;
}

__global__ void reorder_kernel() {
    int e = blockIdx.x * blockDim.x + threadIdx.x;
    if (e >= N_EDGES) return;
    int d = g_eidx[N_EDGES + e];
    int pos = atomicAdd(&g_cur[d], 1);
    g_csrc[pos] = g_eidx[e];
}

// ---------------------------------------------------------------
// weight + bias prep: W1=[Wl1|Wr1], W2=[Wl2;Wr2] as bf16 hi/lo
// ---------------------------------------------------------------
__global__ void convW_kernel(const float* __restrict__ Wl1, const float* __restrict__ Wr1,
                             const float* __restrict__ Wl2, const float* __restrict__ Wr2,
                             const float* __restrict__ bl1, const float* __restrict__ bl2) {
    int i = blockIdx.x * blockDim.x + threadIdx.x;
    if (i < 2 * 256 * 256) {
        int op = i >> 16;
        int rem = i & 65535;
        int n = rem >> 8, k = rem & 255;
        float w;
        if (op == 0) w = (k < 128) ? Wl1[n * 128 + k] : Wr1[n * 128 + (k - 128)];
        else         w = (n < 128) ? Wl2[n * 256 + k] : Wr2[(n - 128) * 256 + k];
        unsigned short h, l;
        f2bf2(w, h, l);
        if (op == 0) { g_W1hi[rem] = h; g_W1lo[rem] = l; }
        else         { g_W2hi[rem] = h; g_W2lo[rem] = l; }
    }
    if (i < 256) g_b1[i] = bl1[i];
    else if (i < 512) {
        int n = i - 256;
        g_b2[n] = (n < 128) ? 0.0f : bl2[n - 128];
    }
}

// x -> A1 cols 128..255 (bf16 hi/lo)
__global__ void xconv_kernel(const float* __restrict__ x) {
    int i4 = blockIdx.x * blockDim.x + threadIdx.x;
    if (i4 >= N_NODES * 32) return;
    int m = i4 >> 5, c4 = i4 & 31;
    float4 v = ((const float4*)x)[i4];
    unsigned short h0, l0, h1, l1, h2, l2, h3, l3;
    f2bf2(v.x, h0, l0); f2bf2(v.y, h1, l1);
    f2bf2(v.z, h2, l2); f2bf2(v.w, h3, l3);
    size_t base = (size_t)m * 128 + 64 + c4 * 2;
    g_A1hi[base]     = (unsigned)h0 | ((unsigned)h1 << 16);
    g_A1hi[base + 1] = (unsigned)h2 | ((unsigned)h3 << 16);
    g_A1lo[base]     = (unsigned)l0 | ((unsigned)l1 << 16);
    g_A1lo[base + 1] = (unsigned)l2 | ((unsigned)l3 << 16);
}

// ---------------------------------------------------------------
// gather1: mean = (sum x[neighbors]) * dinv -> A1 cols 0..127 bf16 hi/lo
// ---------------------------------------------------------------
__global__ void gather1_kernel(const float* __restrict__ feat) {
    int warp = (blockIdx.x * blockDim.x + threadIdx.x) >> 5;
    int lane = threadIdx.x & 31;
    if (warp >= N_NODES) return;
    int start = g_row[warp];
    int end = g_row[warp + 1];
    float4 acc = make_float4(0.f, 0.f, 0.f, 0.f);
    for (int base = start; base < end; base += 32) {
        int mye = base + lane;
        int sidx = (mye < end) ? g_csrc[mye] : 0;
        int cnt = end - base; if (cnt > 32) cnt = 32;
#pragma unroll 4
        for (int j = 0; j < cnt; j++) {
            int s = __shfl_sync(0xffffffffu, sidx, j);
            float4 v = __ldg((const float4*)(feat + (size_t)s * 128) + lane);
            acc.x += v.x; acc.y += v.y; acc.z += v.z; acc.w += v.w;
        }
    }
    float sc = g_dinv[warp];
    acc.x *= sc; acc.y *= sc; acc.z *= sc; acc.w *= sc;
    unsigned short h0, l0, h1, l1, h2, l2, h3, l3;
    f2bf2(acc.x, h0, l0); f2bf2(acc.y, h1, l1);
    f2bf2(acc.z, h2, l2); f2bf2(acc.w, h3, l3);
    size_t base = (size_t)warp * 128 + lane * 2;
    g_A1hi[base]     = (unsigned)h0 | ((unsigned)h1 << 16);
    g_A1hi[base + 1] = (unsigned)h2 | ((unsigned)h3 << 16);
    g_A1lo[base]     = (unsigned)l0 | ((unsigned)l1 << 16);
    g_A1lo[base + 1] = (unsigned)l2 | ((unsigned)l3 << 16);
}

// gather2: msg2g[n] = sum p[neighbors]   (p = g_out2 cols 0..127, stride 256)
__global__ void gather2_kernel() {
    int warp = (blockIdx.x * blockDim.x + threadIdx.x) >> 5;
    int lane = threadIdx.x & 31;
    if (warp >= N_NODES) return;
    int start = g_row[warp];
    int end = g_row[warp + 1];
    float4 acc = make_float4(0.f, 0.f, 0.f, 0.f);
    for (int base = start; base < end; base += 32) {
        int mye = base + lane;
        int sidx = (mye < end) ? g_csrc[mye] : 0;
        int cnt = end - base; if (cnt > 32) cnt = 32;
#pragma unroll 4
        for (int j = 0; j < cnt; j++) {
            int s = __shfl_sync(0xffffffffu, sidx, j);
            float4 v = __ldg((const float4*)(g_out2 + (size_t)s * 256) + lane);
            acc.x += v.x; acc.y += v.y; acc.z += v.z; acc.w += v.w;
        }
    }
    ((float4*)(g_msg2g + (size_t)warp * 128))[lane] = acc;
}

// final: out = msg2g*dinv + q   (q = g_out2 cols 128..255)
__global__ void final_kernel(float* __restrict__ out) {
    int i4 = blockIdx.x * blockDim.x + threadIdx.x;
    if (i4 >= N_NODES * 32) return;
    int m = i4 >> 5, c4 = i4 & 31;
    float s = g_dinv[m];
    float4 mm = ((const float4*)g_msg2g)[i4];
    float4 qq = *(const float4*)(g_out2 + (size_t)m * 256 + 128 + c4 * 4);
    float4 o;
    o.x = mm.x * s + qq.x;
    o.y = mm.y * s + qq.y;
    o.z = mm.z * s + qq.z;
    o.w = mm.w * s + qq.w;
    ((float4*)out)[i4] = o;
}

// ---------------------------------------------------------------
// mma.sync bf16 GEMM: C[M,256] = Ah@Whᵀ + Al@Whᵀ + Ah@Wlᵀ (+bias)
// A: bf16 [M,256] hi/lo (rows = 32 uint4), W: bf16 [256,256] hi/lo.
// CTA 128x128, 8 warps (4M x 2N), warp tile 32x64, BK=32, dbl-buffered.
// mode 0: fp32 out (stride 256) + bias
// mode 1: bf16 hi/lo out (stride 128 uints), ReLU(v + bias)
// ---------------------------------------------------------------
#define SSTR 40   // smem row stride in halves (32 + 8 pad)

__global__ void __launch_bounds__(256) gemm_mma_kernel(
    const uint4* __restrict__ Ahi, const uint4* __restrict__ Alo,
    const uint4* __restrict__ Whi, const uint4* __restrict__ Wlo,
    const float* __restrict__ bias,
    float* __restrict__ outF,
    unsigned* __restrict__ outHi, unsigned* __restrict__ outLo,
    int M, int mode) {
    __shared__ __align__(16) unsigned short As[2][128 * SSTR];
    __shared__ __align__(16) unsigned short Bs[2][128 * SSTR];
    __shared__ float bsm[128];

    int tid = threadIdx.x;
    int wid = tid >> 5, lane = tid & 31;
    int wy = wid & 3, wx = wid >> 2;       // warp: rows wy*32, cols wx*64
    int tig = lane & 3, grp = lane >> 2;
    int m0 = blockIdx.y * 128;
    int n0 = blockIdx.x * 128;

    if (tid < 128) bsm[tid] = bias[n0 + tid];

    float acc[2][8][4];
#pragma unroll
    for (int a = 0; a < 2; a++)
#pragma unroll
        for (int b = 0; b < 8; b++)
#pragma unroll
            for (int c = 0; c < 4; c++) acc[a][b][c] = 0.f;

    int lrow = tid >> 1;                   // load assignment: thread covers
    int lq0 = (tid & 1) * 2;               // rows tid/2, uint4 q = lq0, lq0+1

    uint4 ra[2], rb[2];

#define LOADC(cc) do {                                                          \
        int term_ = (cc) >> 3, kb_ = (cc) & 7;                                  \
        const uint4* A4_ = (term_ == 1) ? Alo : Ahi;                            \
        const uint4* W4_ = (term_ == 2) ? Wlo : Whi;                            \
        int gm_ = m0 + lrow; if (gm_ >= M) gm_ = M - 1;                         \
        ra[0] = __ldg(&A4_[(size_t)gm_ * 32 + kb_ * 4 + lq0]);                  \
        ra[1] = __ldg(&A4_[(size_t)gm_ * 32 + kb_ * 4 + lq0 + 1]);              \
        rb[0] = __ldg(&W4_[(size_t)(n0 + lrow) * 32 + kb_ * 4 + lq0]);          \
        rb[1] = __ldg(&W4_[(size_t)(n0 + lrow) * 32 + kb_ * 4 + lq0 + 1]);      \
    } while (0)

#define STOREC(bb) do {                                                         \
        *(uint4*)&As[bb][lrow * SSTR + lq0 * 8]       = ra[0];                  \
        *(uint4*)&As[bb][lrow * SSTR + (lq0 + 1) * 8] = ra[1];                  \
        *(uint4*)&Bs[bb][lrow * SSTR + lq0 * 8]       = rb[0];                  \
        *(uint4*)&Bs[bb][lrow * SSTR + (lq0 + 1) * 8] = rb[1];                  \
    } while (0)

    LOADC(0);
    STOREC(0);
    __syncthreads();

    for (int c = 0; c < 24; c++) {
        int b = c & 1;
        if (c < 23) LOADC(c + 1);

        const unsigned short* As_ = As[b];
        const unsigned short* Bs_ = Bs[b];
#pragma unroll
        for (int ks = 0; ks < 2; ks++) {
            unsigned af[2][4];
#pragma unroll
            for (int mt = 0; mt < 2; mt++) {
                const unsigned short* pa =
                    As_ + (wy * 32 + mt * 16 + grp) * SSTR + ks * 16 + tig * 2;
                af[mt][0] = *(const unsigned*)pa;
                af[mt][1] = *(const unsigned*)(pa + 8 * SSTR);
                af[mt][2] = *(const unsigned*)(pa + 8);
                af[mt][3] = *(const unsigned*)(pa + 8 * SSTR + 8);
            }
#pragma unroll
            for (int nt = 0; nt < 8; nt++) {
                const unsigned short* pb =
                    Bs_ + (wx * 64 + nt * 8 + grp) * SSTR + ks * 16 + tig * 2;
                unsigned b0 = *(const unsigned*)pb;
                unsigned b1 = *(const unsigned*)(pb + 8);
#pragma unroll
                for (int mt = 0; mt < 2; mt++) {
                    asm volatile(
                        "mma.sync.aligned.m16n8k16.row.col.f32.bf16.bf16.f32 "
                        "{%0,%1,%2,%3}, {%4,%5,%6,%7}, {%8,%9}, {%0,%1,%2,%3};"
                        : "+f"(acc[mt][nt][0]), "+f"(acc[mt][nt][1]),
                          "+f"(acc[mt][nt][2]), "+f"(acc[mt][nt][3])
                        : "r"(af[mt][0]), "r"(af[mt][1]),
                          "r"(af[mt][2]), "r"(af[mt][3]),
                          "r"(b0), "r"(b1));
                }
            }
        }

        if (c < 23) {
            __syncthreads();
            STOREC((c + 1) & 1);
            __syncthreads();
        }
    }

    // epilogue
#pragma unroll
    for (int mt = 0; mt < 2; mt++) {
        int gm0 = m0 + wy * 32 + mt * 16 + grp;   // and gm0+8
#pragma unroll
        for (int nt = 0; nt < 8; nt++) {
            int nl = wx * 64 + nt * 8 + tig * 2;  // local col (even)
            int gn = n0 + nl;
            float bx = bsm[nl], by = bsm[nl + 1];
            float v0 = acc[mt][nt][0] + bx;
            float v1 = acc[mt][nt][1] + by;
            float v2 = acc[mt][nt][2] + bx;
            float v3 = acc[mt][nt][3] + by;
            if (mode == 1) {
                v0 = fmaxf(v0, 0.f); v1 = fmaxf(v1, 0.f);
                v2 = fmaxf(v2, 0.f); v3 = fmaxf(v3, 0.f);
            }
            if (mode == 0) {
                if (gm0 < M)
                    *(float2*)(outF + (size_t)gm0 * 256 + gn) = make_float2(v0, v1);
                if (gm0 + 8 < M)
                    *(float2*)(outF + (size_t)(gm0 + 8) * 256 + gn) = make_float2(v2, v3);
            } else {
                unsigned short h0, l0, h1, l1;
                if (gm0 < M) {
                    f2bf2(v0, h0, l0); f2bf2(v1, h1, l1);
                    size_t idx = (size_t)gm0 * 128 + (gn >> 1);
                    outHi[idx] = (unsigned)h0 | ((unsigned)h1 << 16);
                    outLo[idx] = (unsigned)l0 | ((unsigned)l1 << 16);
                }
                if (gm0 + 8 < M) {
                    f2bf2(v2, h0, l0); f2bf2(v3, h1, l1);
                    size_t idx = (size_t)(gm0 + 8) * 128 + (gn >> 1);
                    outHi[idx] = (unsigned)h0 | ((unsigned)h1 << 16);
                    outLo[idx] = (unsigned)l0 | ((unsigned)l1 << 16);
                }
            }
        }
    }
#undef LOADC
#undef STOREC
}

// ---------------------------------------------------------------
// launch — inputs: x, Wl1, bl1, Wr1, Wl2, bl2, Wr2, edge_index
// ---------------------------------------------------------------
extern "C" void kernel_launch(void* const* d_in, const int* in_sizes, int n_in,
                              void* d_out, int out_size) {
    const float* x   = (const float*)d_in[0];
    const float* Wl1 = (const float*)d_in[1];
    const float* bl1 = (const float*)d_in[2];
    const float* Wr1 = (const float*)d_in[3];
    const float* Wl2 = (const float*)d_in[4];
    const float* bl2 = (const float*)d_in[5];
    const float* Wr2 = (const float*)d_in[6];
    const void*  ei  = d_in[7];
    float* out = (float*)d_out;

    unsigned *A1hi, *A1lo, *A2hi, *A2lo;
    unsigned short *W1hi, *W1lo, *W2hi, *W2lo;
    float *b1, *b2, *out2;
    cudaGetSymbolAddress((void**)&A1hi, g_A1hi);
    cudaGetSymbolAddress((void**)&A1lo, g_A1lo);
    cudaGetSymbolAddress((void**)&A2hi, g_A2hi);
    cudaGetSymbolAddress((void**)&A2lo, g_A2lo);
    cudaGetSymbolAddress((void**)&W1hi, g_W1hi);
    cudaGetSymbolAddress((void**)&W1lo, g_W1lo);
    cudaGetSymbolAddress((void**)&W2hi, g_W2hi);
    cudaGetSymbolAddress((void**)&W2lo, g_W2lo);
    cudaGetSymbolAddress((void**)&b1, g_b1);
    cudaGetSymbolAddress((void**)&b2, g_b2);
    cudaGetSymbolAddress((void**)&out2, g_out2);

    // 0. decode edges + degree
    detect_kernel<<<1, 32>>>((const int*)ei);
    zero_deg_kernel<<<(N_NODES + 255) / 256, 256>>>();
    convert_kernel<<<(2 * N_EDGES + 255) / 256, 256>>>(ei);

    // 1. CSR build
    scan_blocks_kernel<<<SCAN_NB, 256>>>();
    scan_tops_kernel<<<1, 256>>>();
    scan_finish_kernel<<<SCAN_NB, 256>>>();
    reorder_kernel<<<(N_EDGES + 255) / 256, 256>>>();

    // 2. weight/bias prep + x split
    convW_kernel<<<(2 * 256 * 256 + 255) / 256, 256>>>(Wl1, Wr1, Wl2, Wr2, bl1, bl2);
    xconv_kernel<<<(N_NODES * 32 + 255) / 256, 256>>>(x);

    // 3. layer-1 gather -> A1 cols 0..127 (mean*dinv, bf16 split)
    gather1_kernel<<<(N_NODES + 7) / 8, 256>>>(x);

    // 4. GEMM1: h = relu([mean|x]@[Wl1|Wr1]ᵀ + b1) -> A2 (bf16 split)
    {
        dim3 grid(2, GEMM_MB);
        gemm_mma_kernel<<<grid, 256>>>((const uint4*)A1hi, (const uint4*)A1lo,
                                       (const uint4*)W1hi, (const uint4*)W1lo,
                                       b1, nullptr, A2hi, A2lo, N_NODES, 1);
    }

    // 5. GEMM2: [p|q] = h@[Wl2;Wr2]ᵀ + [0|bl2] -> out2 fp32
    {
        dim3 grid(2, GEMM_MB);
        gemm_mma_kernel<<<grid, 256>>>((const uint4*)A2hi, (const uint4*)A2lo,
                                       (const uint4*)W2hi, (const uint4*)W2lo,
                                       b2, out2, nullptr, nullptr, N_NODES, 0);
    }

    // 6. layer-2 gather on p
    gather2_kernel<<<(N_NODES + 7) / 8, 256>>>();

    // 7. out = msg2g*dinv + q
    final_kernel<<<(N_NODES * 32 + 255) / 256, 256>>>(out);
}

// round 8
// speedup vs baseline: 2.1070x; 1.2067x over previous
#include <cuda_runtime.h>
#include <cuda_bf16.h>
#include <cstdint>
#include <cstddef>

#define N_NODES 50000
#define N_EDGES 800000
#define SCAN_NB ((N_NODES + 255) / 256)   // 196 blocks
#define GEMM_MB ((N_NODES + 127) / 128)   // 391 CTAs in M

// ---- device scratch ----
__device__ __align__(16) unsigned g_A1hi[(size_t)N_NODES * 128];
__device__ __align__(16) unsigned g_A1lo[(size_t)N_NODES * 128];
__device__ __align__(16) unsigned g_A2hi[(size_t)N_NODES * 128];
__device__ __align__(16) unsigned g_A2lo[(size_t)N_NODES * 128];
__device__ __align__(16) float    g_out2[(size_t)N_NODES * 256];   // [p|q] fp32
__device__ __align__(16) unsigned short g_W1hi[256 * 256];
__device__ __align__(16) unsigned short g_W1lo[256 * 256];
__device__ __align__(16) unsigned short g_W2hi[256 * 256];
__device__ __align__(16) unsigned short g_W2lo[256 * 256];
__device__ __align__(16) float g_b1[256];
__device__ __align__(16) float g_b2[256];
__device__ __align__(16) float g_dinv[N_NODES];
__device__ __align__(16) int   g_eidx[2 * N_EDGES];
__device__ __align__(16) int   g_degi[N_NODES];
__device__ __align__(16) int   g_row[N_NODES + 1];
__device__ __align__(16) int   g_cur[N_NODES];
__device__ __align__(16) int   g_csrc[N_EDGES];
__device__ __align__(16) int   g_bsum[SCAN_NB];
__device__ __align__(16) int   g_boff[256];
__device__ int g_fmt;

// ---------------- helpers ----------------
__device__ __forceinline__ void f2bf2(float v, unsigned short& h, unsigned short& l) {
    __nv_bfloat16 hb = __float2bfloat16(v);
    float hf = __bfloat162float(hb);
    __nv_bfloat16 lb = __float2bfloat16(v - hf);
    h = *reinterpret_cast<unsigned short*>(&hb);
    l = *reinterpret_cast<unsigned short*>(&lb);
}

__device__ __forceinline__ unsigned su32(const void* p) {
    return (unsigned)__cvta_generic_to_shared(p);
}

// ---------------------------------------------------------------
// edge decode + CSR build
// ---------------------------------------------------------------
__global__ void detect_kernel(const int* __restrict__ ei32) {
    if (threadIdx.x == 0 && blockIdx.x == 0) {
        int odd_nonzero = 0;
        for (int i = 0; i < 512; i++) odd_nonzero += (ei32[2 * i + 1] != 0);
        g_fmt = (odd_nonzero == 0) ? 1 : 0;
    }
}

__global__ void zero_deg_kernel() {
    int i = blockIdx.x * blockDim.x + threadIdx.x;
    if (i < N_NODES) g_degi[i] = 0;
}

__global__ void convert_kernel(const void* __restrict__ ei) {
    int i = blockIdx.x * blockDim.x + threadIdx.x;
    if (i >= 2 * N_EDGES) return;
    int v;
    if (g_fmt) v = (int)((const long long*)ei)[i];
    else       v = ((const int*)ei)[i];
    g_eidx[i] = v;
    if (i >= N_EDGES) atomicAdd(&g_degi[v], 1);
}

__global__ void scan_blocks_kernel() {
    __shared__ int s[256];
    int t = threadIdx.x;
    int i = blockIdx.x * 256 + t;
    int v = (i < N_NODES) ? g_degi[i] : 0;
    s[t] = v;
    __syncthreads();
#pragma unroll
    for (int off = 1; off < 256; off <<= 1) {
        int add = (t >= off) ? s[t - off] : 0;
        __syncthreads();
        s[t] += add;
        __syncthreads();
    }
    int incl = s[t];
    if (i < N_NODES) g_row[i] = incl - v;
    if (t == 255) g_bsum[blockIdx.x] = incl;
}

__global__ void scan_tops_kernel() {
    __shared__ int s[256];
    int t = threadIdx.x;
    int v = (t < SCAN_NB) ? g_bsum[t] : 0;
    s[t] = v;
    __syncthreads();
#pragma unroll
    for (int off = 1; off < 256; off <<= 1) {
        int add = (t >= off) ? s[t - off] : 0;
        __syncthreads();
        s[t] += add;
        __syncthreads();
    }
    if (t < SCAN_NB) g_boff[t] = s[t] - v;
}

__global__ void scan_finish_kernel() {
    int i = blockIdx.x * 256 + threadIdx.x;
    if (i < N_NODES) {
        int r = g_row[i] + g_boff[blockIdx.x];
        g_row[i] = r;
        g_cur[i] = r;
        g_dinv[i] = 1.0f / fmaxf((float)g_degi[i], 1.0f);
    }
    if (i == 0) g_row[N_NODES] = N_EDGES;
}

__global__ void reorder_kernel() {
    int e = blockIdx.x * blockDim.x + threadIdx.x;
    if (e >= N_EDGES) return;
    int d = g_eidx[N_EDGES + e];
    int pos = atomicAdd(&g_cur[d], 1);
    g_csrc[pos] = g_eidx[e];
}

// ---------------------------------------------------------------
// weight + bias prep
// ---------------------------------------------------------------
__global__ void convW_kernel(const float* __restrict__ Wl1, const float* __restrict__ Wr1,
                             const float* __restrict__ Wl2, const float* __restrict__ Wr2,
                             const float* __restrict__ bl1, const float* __restrict__ bl2) {
    int i = blockIdx.x * blockDim.x + threadIdx.x;
    if (i < 2 * 256 * 256) {
        int op = i >> 16;
        int rem = i & 65535;
        int n = rem >> 8, k = rem & 255;
        float w;
        if (op == 0) w = (k < 128) ? Wl1[n * 128 + k] : Wr1[n * 128 + (k - 128)];
        else         w = (n < 128) ? Wl2[n * 256 + k] : Wr2[(n - 128) * 256 + k];
        unsigned short h, l;
        f2bf2(w, h, l);
        if (op == 0) { g_W1hi[rem] = h; g_W1lo[rem] = l; }
        else         { g_W2hi[rem] = h; g_W2lo[rem] = l; }
    }
    if (i < 256) g_b1[i] = bl1[i];
    else if (i < 512) {
        int n = i - 256;
        g_b2[n] = (n < 128) ? 0.0f : bl2[n - 128];
    }
}

// ---------------------------------------------------------------
// gather1 (+ fused x conversion): A1 = [bf16split(mean) | bf16split(x)]
// ---------------------------------------------------------------
__global__ void gather1_kernel(const float* __restrict__ feat) {
    int warp = (blockIdx.x * blockDim.x + threadIdx.x) >> 5;
    int lane = threadIdx.x & 31;
    if (warp >= N_NODES) return;

    // own x row -> cols 128..255
    {
        float4 v = __ldg((const float4*)(feat + (size_t)warp * 128) + lane);
        unsigned short h0, l0, h1, l1, h2, l2, h3, l3;
        f2bf2(v.x, h0, l0); f2bf2(v.y, h1, l1);
        f2bf2(v.z, h2, l2); f2bf2(v.w, h3, l3);
        size_t base = (size_t)warp * 128 + 64 + lane * 2;
        g_A1hi[base]     = (unsigned)h0 | ((unsigned)h1 << 16);
        g_A1hi[base + 1] = (unsigned)h2 | ((unsigned)h3 << 16);
        g_A1lo[base]     = (unsigned)l0 | ((unsigned)l1 << 16);
        g_A1lo[base + 1] = (unsigned)l2 | ((unsigned)l3 << 16);
    }

    int start = g_row[warp];
    int end = g_row[warp + 1];
    float4 acc = make_float4(0.f, 0.f, 0.f, 0.f);
    for (int base = start; base < end; base += 32) {
        int mye = base + lane;
        int sidx = (mye < end) ? g_csrc[mye] : 0;
        int cnt = end - base; if (cnt > 32) cnt = 32;
#pragma unroll 4
        for (int j = 0; j < cnt; j++) {
            int s = __shfl_sync(0xffffffffu, sidx, j);
            float4 v = __ldg((const float4*)(feat + (size_t)s * 128) + lane);
            acc.x += v.x; acc.y += v.y; acc.z += v.z; acc.w += v.w;
        }
    }
    float sc = g_dinv[warp];
    acc.x *= sc; acc.y *= sc; acc.z *= sc; acc.w *= sc;
    unsigned short h0, l0, h1, l1, h2, l2, h3, l3;
    f2bf2(acc.x, h0, l0); f2bf2(acc.y, h1, l1);
    f2bf2(acc.z, h2, l2); f2bf2(acc.w, h3, l3);
    size_t base = (size_t)warp * 128 + lane * 2;
    g_A1hi[base]     = (unsigned)h0 | ((unsigned)h1 << 16);
    g_A1hi[base + 1] = (unsigned)h2 | ((unsigned)h3 << 16);
    g_A1lo[base]     = (unsigned)l0 | ((unsigned)l1 << 16);
    g_A1lo[base + 1] = (unsigned)l2 | ((unsigned)l3 << 16);
}

// ---------------------------------------------------------------
// gather2 + final: out[n] = (sum p[nb]) * dinv[n] + q[n]
// p = g_out2 cols 0..127, q = cols 128..255
// ---------------------------------------------------------------
__global__ void gather2_kernel(float* __restrict__ out) {
    int warp = (blockIdx.x * blockDim.x + threadIdx.x) >> 5;
    int lane = threadIdx.x & 31;
    if (warp >= N_NODES) return;
    int start = g_row[warp];
    int end = g_row[warp + 1];
    float4 acc = make_float4(0.f, 0.f, 0.f, 0.f);
    for (int base = start; base < end; base += 32) {
        int mye = base + lane;
        int sidx = (mye < end) ? g_csrc[mye] : 0;
        int cnt = end - base; if (cnt > 32) cnt = 32;
#pragma unroll 4
        for (int j = 0; j < cnt; j++) {
            int s = __shfl_sync(0xffffffffu, sidx, j);
            float4 v = __ldg((const float4*)(g_out2 + (size_t)s * 256) + lane);
            acc.x += v.x; acc.y += v.y; acc.z += v.z; acc.w += v.w;
        }
    }
    float s = g_dinv[warp];
    float4 q = *(const float4*)(g_out2 + (size_t)warp * 256 + 128 + lane * 4);
    float4 o;
    o.x = acc.x * s + q.x;
    o.y = acc.y * s + q.y;
    o.z = acc.z * s + q.z;
    o.w = acc.w * s + q.w;
    ((float4*)(out + (size_t)warp * 128))[lane] = o;
}

// ---------------------------------------------------------------
// mma.sync bf16 GEMM with cp.async + ldmatrix.
// C[M,256] = Ah@Whᵀ + Al@Whᵀ + Ah@Wlᵀ (+bias)
// CTA 128x128, 8 warps (4M x 2N), warp 32x64, BK=32, 2-stage cp.async.
// mode 0: fp32 out (stride 256) + bias;  mode 1: ReLU->bf16 hi/lo out.
// ---------------------------------------------------------------
#define SSTR 40   // smem row stride in halves (64B data + 16B pad)
#define NCH 24    // k-chunks: 3 terms x 8

__global__ void __launch_bounds__(256, 2) gemm_mma_kernel(
    const uint4* __restrict__ Ahi, const uint4* __restrict__ Alo,
    const uint4* __restrict__ Whi, const uint4* __restrict__ Wlo,
    const float* __restrict__ bias,
    float* __restrict__ outF,
    unsigned* __restrict__ outHi, unsigned* __restrict__ outLo,
    int M, int mode) {
    __shared__ __align__(16) unsigned short As[2][128 * SSTR];
    __shared__ __align__(16) unsigned short Bs[2][128 * SSTR];
    __shared__ float bsm[128];

    int tid = threadIdx.x;
    int wid = tid >> 5, lane = tid & 31;
    int wy = wid & 3, wx = wid >> 2;
    int tig = lane & 3, grp = lane >> 2;
    int m0 = blockIdx.y * 128;
    int n0 = blockIdx.x * 128;

    if (tid < 128) bsm[tid] = bias[n0 + tid];

    float acc[2][8][4];
#pragma unroll
    for (int a = 0; a < 2; a++)
#pragma unroll
        for (int b = 0; b < 8; b++)
#pragma unroll
            for (int c = 0; c < 4; c++) acc[a][b][c] = 0.f;

    // load assignment: thread covers row tid/2, 16B chunks lc0, lc0+1
    int lrow = tid >> 1;
    int lc0 = (tid & 1) * 2;
    int gmA = m0 + lrow; if (gmA >= M) gmA = M - 1;
    size_t aRow = (size_t)gmA * 32;
    size_t bRow = (size_t)(n0 + lrow) * 32;

#define ISSUE(ss) do {                                                         \
        int term_ = (ss) >> 3, kb_ = (ss) & 7;                                 \
        const uint4* A4_ = (term_ == 1) ? Alo : Ahi;                           \
        const uint4* W4_ = (term_ == 2) ? Wlo : Whi;                           \
        unsigned da = su32(&As[(ss) & 1][lrow * SSTR + lc0 * 8]);              \
        unsigned db = su32(&Bs[(ss) & 1][lrow * SSTR + lc0 * 8]);              \
        const uint4* sa = &A4_[aRow + kb_ * 4 + lc0];                          \
        const uint4* sb = &W4_[bRow + kb_ * 4 + lc0];                          \
        asm volatile("cp.async.cg.shared.global [%0], [%1], 16;" :: "r"(da), "l"(sa)); \
        asm volatile("cp.async.cg.shared.global [%0], [%1], 16;" :: "r"(da + 16), "l"(sa + 1)); \
        asm volatile("cp.async.cg.shared.global [%0], [%1], 16;" :: "r"(db), "l"(sb)); \
        asm volatile("cp.async.cg.shared.global [%0], [%1], 16;" :: "r"(db + 16), "l"(sb + 1)); \
        asm volatile("cp.async.commit_group;");                                \
    } while (0)

    ISSUE(0);

    // ldmatrix source addresses (per buffer)
    int arow = wy * 32 + (lane & 15);          // + mt*16
    int acol = (lane >> 4);                     // 16B chunk + ks*2
    int brow = wx * 64 + ((lane >> 4) & 1) * 8 + (lane & 7);  // + g*16
    int bcol = (lane >> 3) & 1;                 // + ks*2

    for (int c = 0; c < NCH; c++) {
        int b = c & 1;
        if (c + 1 < NCH) {
            ISSUE(c + 1);
            asm volatile("cp.async.wait_group 1;");
        } else {
            asm volatile("cp.async.wait_group 0;");
        }
        __syncthreads();

        const unsigned short* As_ = As[b];
        const unsigned short* Bs_ = Bs[b];
#pragma unroll
        for (int ks = 0; ks < 2; ks++) {
            unsigned af[2][4];
#pragma unroll
            for (int mt = 0; mt < 2; mt++) {
                unsigned addr = su32(&As_[(arow + mt * 16) * SSTR + (ks * 2 + acol) * 8]);
                asm volatile(
                    "ldmatrix.sync.aligned.m8n8.x4.shared.b16 {%0,%1,%2,%3}, [%4];"
                    : "=r"(af[mt][0]), "=r"(af[mt][1]), "=r"(af[mt][2]), "=r"(af[mt][3])
                    : "r"(addr));
            }
#pragma unroll
            for (int g = 0; g < 4; g++) {
                unsigned bf[4];
                unsigned addr = su32(&Bs_[(brow + g * 16) * SSTR + (ks * 2 + bcol) * 8]);
                asm volatile(
                    "ldmatrix.sync.aligned.m8n8.x4.shared.b16 {%0,%1,%2,%3}, [%4];"
                    : "=r"(bf[0]), "=r"(bf[1]), "=r"(bf[2]), "=r"(bf[3])
                    : "r"(addr));
#pragma unroll
                for (int mt = 0; mt < 2; mt++) {
                    asm volatile(
                        "mma.sync.aligned.m16n8k16.row.col.f32.bf16.bf16.f32 "
                        "{%0,%1,%2,%3}, {%4,%5,%6,%7}, {%8,%9}, {%0,%1,%2,%3};"
                        : "+f"(acc[mt][2 * g][0]), "+f"(acc[mt][2 * g][1]),
                          "+f"(acc[mt][2 * g][2]), "+f"(acc[mt][2 * g][3])
                        : "r"(af[mt][0]), "r"(af[mt][1]),
                          "r"(af[mt][2]), "r"(af[mt][3]),
                          "r"(bf[0]), "r"(bf[1]));
                    asm volatile(
                        "mma.sync.aligned.m16n8k16.row.col.f32.bf16.bf16.f32 "
                        "{%0,%1,%2,%3}, {%4,%5,%6,%7}, {%8,%9}, {%0,%1,%2,%3};"
                        : "+f"(acc[mt][2 * g + 1][0]), "+f"(acc[mt][2 * g + 1][1]),
                          "+f"(acc[mt][2 * g + 1][2]), "+f"(acc[mt][2 * g + 1][3])
                        : "r"(af[mt][0]), "r"(af[mt][1]),
                          "r"(af[mt][2]), "r"(af[mt][3]),
                          "r"(bf[2]), "r"(bf[3]));
                }
            }
        }
        if (c + 1 < NCH) __syncthreads();
    }

    // epilogue
#pragma unroll
    for (int mt = 0; mt < 2; mt++) {
        int gm0 = m0 + wy * 32 + mt * 16 + grp;
#pragma unroll
        for (int nt = 0; nt < 8; nt++) {
            int nl = wx * 64 + nt * 8 + tig * 2;
            int gn = n0 + nl;
            float bx = bsm[nl], by = bsm[nl + 1];
            float v0 = acc[mt][nt][0] + bx;
            float v1 = acc[mt][nt][1] + by;
            float v2 = acc[mt][nt][2] + bx;
            float v3 = acc[mt][nt][3] + by;
            if (mode == 1) {
                v0 = fmaxf(v0, 0.f); v1 = fmaxf(v1, 0.f);
                v2 = fmaxf(v2, 0.f); v3 = fmaxf(v3, 0.f);
            }
            if (mode == 0) {
                if (gm0 < M)
                    *(float2*)(outF + (size_t)gm0 * 256 + gn) = make_float2(v0, v1);
                if (gm0 + 8 < M)
                    *(float2*)(outF + (size_t)(gm0 + 8) * 256 + gn) = make_float2(v2, v3);
            } else {
                unsigned short h0, l0, h1, l1;
                if (gm0 < M) {
                    f2bf2(v0, h0, l0); f2bf2(v1, h1, l1);
                    size_t idx = (size_t)gm0 * 128 + (gn >> 1);
                    outHi[idx] = (unsigned)h0 | ((unsigned)h1 << 16);
                    outLo[idx] = (unsigned)l0 | ((unsigned)l1 << 16);
                }
                if (gm0 + 8 < M) {
                    f2bf2(v2, h0, l0); f2bf2(v3, h1, l1);
                    size_t idx = (size_t)(gm0 + 8) * 128 + (gn >> 1);
                    outHi[idx] = (unsigned)h0 | ((unsigned)h1 << 16);
                    outLo[idx] = (unsigned)l0 | ((unsigned)l1 << 16);
                }
            }
        }
    }
#undef ISSUE
}

// ---------------------------------------------------------------
// launch — inputs: x, Wl1, bl1, Wr1, Wl2, bl2, Wr2, edge_index
// ---------------------------------------------------------------
extern "C" void kernel_launch(void* const* d_in, const int* in_sizes, int n_in,
                              void* d_out, int out_size) {
    const float* x   = (const float*)d_in[0];
    const float* Wl1 = (const float*)d_in[1];
    const float* bl1 = (const float*)d_in[2];
    const float* Wr1 = (const float*)d_in[3];
    const float* Wl2 = (const float*)d_in[4];
    const float* bl2 = (const float*)d_in[5];
    const float* Wr2 = (const float*)d_in[6];
    const void*  ei  = d_in[7];
    float* out = (float*)d_out;

    unsigned *A1hi, *A1lo, *A2hi, *A2lo;
    unsigned short *W1hi, *W1lo, *W2hi, *W2lo;
    float *b1, *b2, *out2;
    cudaGetSymbolAddress((void**)&A1hi, g_A1hi);
    cudaGetSymbolAddress((void**)&A1lo, g_A1lo);
    cudaGetSymbolAddress((void**)&A2hi, g_A2hi);
    cudaGetSymbolAddress((void**)&A2lo, g_A2lo);
    cudaGetSymbolAddress((void**)&W1hi, g_W1hi);
    cudaGetSymbolAddress((void**)&W1lo, g_W1lo);
    cudaGetSymbolAddress((void**)&W2hi, g_W2hi);
    cudaGetSymbolAddress((void**)&W2lo, g_W2lo);
    cudaGetSymbolAddress((void**)&b1, g_b1);
    cudaGetSymbolAddress((void**)&b2, g_b2);
    cudaGetSymbolAddress((void**)&out2, g_out2);

    // 0. decode edges + degree
    detect_kernel<<<1, 32>>>((const int*)ei);
    zero_deg_kernel<<<(N_NODES + 255) / 256, 256>>>();
    convert_kernel<<<(2 * N_EDGES + 255) / 256, 256>>>(ei);

    // 1. CSR build
    scan_blocks_kernel<<<SCAN_NB, 256>>>();
    scan_tops_kernel<<<1, 256>>>();
    scan_finish_kernel<<<SCAN_NB, 256>>>();
    reorder_kernel<<<(N_EDGES + 255) / 256, 256>>>();

    // 2. weight/bias prep
    convW_kernel<<<(2 * 256 * 256 + 255) / 256, 256>>>(Wl1, Wr1, Wl2, Wr2, bl1, bl2);

    // 3. layer-1 gather + x conversion -> A1
    gather1_kernel<<<(N_NODES + 7) / 8, 256>>>(x);

    // 4. GEMM1: h = relu([mean|x]@[Wl1|Wr1]ᵀ + b1) -> A2 (bf16 split)
    {
        dim3 grid(2, GEMM_MB);
        gemm_mma_kernel<<<grid, 256>>>((const uint4*)A1hi, (const uint4*)A1lo,
                                       (const uint4*)W1hi, (const uint4*)W1lo,
                                       b1, nullptr, A2hi, A2lo, N_NODES, 1);
    }

    // 5. GEMM2: [p|q] = h@[Wl2;Wr2]ᵀ + [0|bl2] -> out2 fp32
    {
        dim3 grid(2, GEMM_MB);
        gemm_mma_kernel<<<grid, 256>>>((const uint4*)A2hi, (const uint4*)A2lo,
                                       (const uint4*)W2hi, (const uint4*)W2lo,
                                       b2, out2, nullptr, nullptr, N_NODES, 0);
    }

    // 6. layer-2 gather on p, fused with final combine
    gather2_kernel<<<(N_NODES + 7) / 8, 256>>>(out);
}

// round 9
// speedup vs baseline: 2.1717x; 1.0307x over previous
#include <cuda_runtime.h>
#include <cuda_bf16.h>
#include <cuda_fp16.h>
#include <cstdint>
#include <cstddef>

#define N_NODES 50000
#define N_EDGES 800000
#define SCAN_NB ((N_NODES + 255) / 256)   // 196 blocks
#define GEMM_MB ((N_NODES + 127) / 128)   // 391 CTAs in M

// ---- device scratch ----
__device__ __align__(16) unsigned g_A1hi[(size_t)N_NODES * 128];
__device__ __align__(16) unsigned g_A1lo[(size_t)N_NODES * 128];
__device__ __align__(16) unsigned g_A2hi[(size_t)N_NODES * 128];
__device__ __align__(16) unsigned g_A2lo[(size_t)N_NODES * 128];
__device__ __align__(16) __half   g_p[(size_t)N_NODES * 128];    // p fp16
__device__ __align__(16) float    g_q[(size_t)N_NODES * 128];    // q fp32
__device__ __align__(16) unsigned short g_W1hi[256 * 256];
__device__ __align__(16) unsigned short g_W1lo[256 * 256];
__device__ __align__(16) unsigned short g_W2hi[256 * 256];
__device__ __align__(16) unsigned short g_W2lo[256 * 256];
__device__ __align__(16) float g_b1[256];
__device__ __align__(16) float g_b2[256];
__device__ __align__(16) float g_dinv[N_NODES];
__device__ __align__(16) int   g_eidx[2 * N_EDGES];
__device__ __align__(16) int   g_degi[N_NODES];
__device__ __align__(16) int   g_row[N_NODES + 1];
__device__ __align__(16) int   g_cur[N_NODES];
__device__ __align__(16) int   g_csrc[N_EDGES];
__device__ __align__(16) int   g_bsum[SCAN_NB];
__device__ __align__(16) int   g_boff[256];
__device__ int g_fmt;

// ---------------- helpers ----------------
__device__ __forceinline__ void f2bf2(float v, unsigned short& h, unsigned short& l) {
    __nv_bfloat16 hb = __float2bfloat16(v);
    float hf = __bfloat162float(hb);
    __nv_bfloat16 lb = __float2bfloat16(v - hf);
    h = *reinterpret_cast<unsigned short*>(&hb);
    l = *reinterpret_cast<unsigned short*>(&lb);
}

__device__ __forceinline__ unsigned su32(const void* p) {
    return (unsigned)__cvta_generic_to_shared(p);
}

// ---------------------------------------------------------------
// init (fused detect + degree zero)
// ---------------------------------------------------------------
__global__ void init_kernel(const int* __restrict__ ei32) {
    int i = blockIdx.x * blockDim.x + threadIdx.x;
    if (i < N_NODES) g_degi[i] = 0;
    if (i == 0) {
        int odd_nonzero = 0;
        for (int k = 0; k < 512; k++) odd_nonzero += (ei32[2 * k + 1] != 0);
        g_fmt = (odd_nonzero == 0) ? 1 : 0;
    }
}

__global__ void convert_kernel(const void* __restrict__ ei) {
    int i = blockIdx.x * blockDim.x + threadIdx.x;
    if (i >= 2 * N_EDGES) return;
    int v;
    if (g_fmt) v = (int)((const long long*)ei)[i];
    else       v = ((const int*)ei)[i];
    g_eidx[i] = v;
    if (i >= N_EDGES) atomicAdd(&g_degi[v], 1);
}

__global__ void scan_blocks_kernel() {
    __shared__ int s[256];
    int t = threadIdx.x;
    int i = blockIdx.x * 256 + t;
    int v = (i < N_NODES) ? g_degi[i] : 0;
    s[t] = v;
    __syncthreads();
#pragma unroll
    for (int off = 1; off < 256; off <<= 1) {
        int add = (t >= off) ? s[t - off] : 0;
        __syncthreads();
        s[t] += add;
        __syncthreads();
    }
    int incl = s[t];
    if (i < N_NODES) g_row[i] = incl - v;
    if (t == 255) g_bsum[blockIdx.x] = incl;
}

__global__ void scan_tops_kernel() {
    __shared__ int s[256];
    int t = threadIdx.x;
    int v = (t < SCAN_NB) ? g_bsum[t] : 0;
    s[t] = v;
    __syncthreads();
#pragma unroll
    for (int off = 1; off < 256; off <<= 1) {
        int add = (t >= off) ? s[t - off] : 0;
        __syncthreads();
        s[t] += add;
        __syncthreads();
    }
    if (t < SCAN_NB) g_boff[t] = s[t] - v;
}

__global__ void scan_finish_kernel() {
    int i = blockIdx.x * 256 + threadIdx.x;
    if (i < N_NODES) {
        int r = g_row[i] + g_boff[blockIdx.x];
        g_row[i] = r;
        g_cur[i] = r;
        g_dinv[i] = 1.0f / fmaxf((float)g_degi[i], 1.0f);
    }
    if (i == 0) g_row[N_NODES] = N_EDGES;
}

__global__ void reorder_kernel() {
    int e = blockIdx.x * blockDim.x + threadIdx.x;
    if (e >= N_EDGES) return;
    int d = g_eidx[N_EDGES + e];
    int pos = atomicAdd(&g_cur[d], 1);
    g_csrc[pos] = g_eidx[e];
}

// ---------------------------------------------------------------
// weight + bias prep
// ---------------------------------------------------------------
__global__ void convW_kernel(const float* __restrict__ Wl1, const float* __restrict__ Wr1,
                             const float* __restrict__ Wl2, const float* __restrict__ Wr2,
                             const float* __restrict__ bl1, const float* __restrict__ bl2) {
    int i = blockIdx.x * blockDim.x + threadIdx.x;
    if (i < 2 * 256 * 256) {
        int op = i >> 16;
        int rem = i & 65535;
        int n = rem >> 8, k = rem & 255;
        float w;
        if (op == 0) w = (k < 128) ? Wl1[n * 128 + k] : Wr1[n * 128 + (k - 128)];
        else         w = (n < 128) ? Wl2[n * 256 + k] : Wr2[(n - 128) * 256 + k];
        unsigned short h, l;
        f2bf2(w, h, l);
        if (op == 0) { g_W1hi[rem] = h; g_W1lo[rem] = l; }
        else         { g_W2hi[rem] = h; g_W2lo[rem] = l; }
    }
    if (i < 256) g_b1[i] = bl1[i];
    else if (i < 512) {
        int n = i - 256;
        g_b2[n] = (n < 128) ? 0.0f : bl2[n - 128];
    }
}

// ---------------------------------------------------------------
// gather1 (+ fused x conversion): A1 = [bf16split(mean) | bf16split(x)]
// ---------------------------------------------------------------
__global__ void gather1_kernel(const float* __restrict__ feat) {
    int warp = (blockIdx.x * blockDim.x + threadIdx.x) >> 5;
    int lane = threadIdx.x & 31;
    if (warp >= N_NODES) return;

    {
        float4 v = __ldg((const float4*)(feat + (size_t)warp * 128) + lane);
        unsigned short h0, l0, h1, l1, h2, l2, h3, l3;
        f2bf2(v.x, h0, l0); f2bf2(v.y, h1, l1);
        f2bf2(v.z, h2, l2); f2bf2(v.w, h3, l3);
        size_t base = (size_t)warp * 128 + 64 + lane * 2;
        g_A1hi[base]     = (unsigned)h0 | ((unsigned)h1 << 16);
        g_A1hi[base + 1] = (unsigned)h2 | ((unsigned)h3 << 16);
        g_A1lo[base]     = (unsigned)l0 | ((unsigned)l1 << 16);
        g_A1lo[base + 1] = (unsigned)l2 | ((unsigned)l3 << 16);
    }

    int start = g_row[warp];
    int end = g_row[warp + 1];
    float4 acc = make_float4(0.f, 0.f, 0.f, 0.f);
    for (int base = start; base < end; base += 32) {
        int mye = base + lane;
        int sidx = (mye < end) ? g_csrc[mye] : 0;
        int cnt = end - base; if (cnt > 32) cnt = 32;
#pragma unroll 4
        for (int j = 0; j < cnt; j++) {
            int s = __shfl_sync(0xffffffffu, sidx, j);
            float4 v = __ldg((const float4*)(feat + (size_t)s * 128) + lane);
            acc.x += v.x; acc.y += v.y; acc.z += v.z; acc.w += v.w;
        }
    }
    float sc = g_dinv[warp];
    acc.x *= sc; acc.y *= sc; acc.z *= sc; acc.w *= sc;
    unsigned short h0, l0, h1, l1, h2, l2, h3, l3;
    f2bf2(acc.x, h0, l0); f2bf2(acc.y, h1, l1);
    f2bf2(acc.z, h2, l2); f2bf2(acc.w, h3, l3);
    size_t base = (size_t)warp * 128 + lane * 2;
    g_A1hi[base]     = (unsigned)h0 | ((unsigned)h1 << 16);
    g_A1hi[base + 1] = (unsigned)h2 | ((unsigned)h3 << 16);
    g_A1lo[base]     = (unsigned)l0 | ((unsigned)l1 << 16);
    g_A1lo[base + 1] = (unsigned)l2 | ((unsigned)l3 << 16);
}

// ---------------------------------------------------------------
// gather2 + final: out[n] = (sum fp16 p[nb]) * dinv[n] + q[n]
// ---------------------------------------------------------------
__global__ void gather2_kernel(float* __restrict__ out) {
    int warp = (blockIdx.x * blockDim.x + threadIdx.x) >> 5;
    int lane = threadIdx.x & 31;
    if (warp >= N_NODES) return;
    int start = g_row[warp];
    int end = g_row[warp + 1];
    float a0 = 0.f, a1 = 0.f, a2 = 0.f, a3 = 0.f;
    for (int base = start; base < end; base += 32) {
        int mye = base + lane;
        int sidx = (mye < end) ? g_csrc[mye] : 0;
        int cnt = end - base; if (cnt > 32) cnt = 32;
#pragma unroll 4
        for (int j = 0; j < cnt; j++) {
            int s = __shfl_sync(0xffffffffu, sidx, j);
            uint2 v = __ldg((const uint2*)(g_p + (size_t)s * 128) + lane);
            float2 f0 = __half22float2(*reinterpret_cast<__half2*>(&v.x));
            float2 f1 = __half22float2(*reinterpret_cast<__half2*>(&v.y));
            a0 += f0.x; a1 += f0.y; a2 += f1.x; a3 += f1.y;
        }
    }
    float s = g_dinv[warp];
    float4 q = __ldg((const float4*)(g_q + (size_t)warp * 128) + lane);
    float4 o;
    o.x = a0 * s + q.x;
    o.y = a1 * s + q.y;
    o.z = a2 * s + q.z;
    o.w = a3 * s + q.w;
    ((float4*)(out + (size_t)warp * 128))[lane] = o;
}

// ---------------------------------------------------------------
// mma.sync bf16 GEMM, 4-stage cp.async + ldmatrix.
// C[M,256] = Ah@Whᵀ + Al@Whᵀ + Ah@Wlᵀ (+bias)
// CTA 128x128, 8 warps (4M x 2N), warp 32x64, BK=32.
// mode 0: p fp16 (n0=0) / q fp32 (n0=128);  mode 1: ReLU->bf16 hi/lo.
// ---------------------------------------------------------------
#define SSTR 40   // smem row stride in halves
#define NCH 24    // k-chunks: 3 terms x 8
#define NSTG 4

__global__ void __launch_bounds__(256, 2) gemm_mma_kernel(
    const uint4* __restrict__ Ahi, const uint4* __restrict__ Alo,
    const uint4* __restrict__ Whi, const uint4* __restrict__ Wlo,
    const float* __restrict__ bias,
    __half* __restrict__ outP, float* __restrict__ outQ,
    unsigned* __restrict__ outHi, unsigned* __restrict__ outLo,
    int M, int mode) {
    __shared__ __align__(16) unsigned short As[NSTG][128 * SSTR];
    __shared__ __align__(16) unsigned short Bs[NSTG][128 * SSTR];
    __shared__ float bsm[128];

    int tid = threadIdx.x;
    int wid = tid >> 5, lane = tid & 31;
    int wy = wid & 3, wx = wid >> 2;
    int tig = lane & 3, grp = lane >> 2;
    int m0 = blockIdx.y * 128;
    int n0 = blockIdx.x * 128;

    if (tid < 128) bsm[tid] = bias[n0 + tid];

    float acc[2][8][4];
#pragma unroll
    for (int a = 0; a < 2; a++)
#pragma unroll
        for (int b = 0; b < 8; b++)
#pragma unroll
            for (int c = 0; c < 4; c++) acc[a][b][c] = 0.f;

    int lrow = tid >> 1;
    int lc0 = (tid & 1) * 2;
    int gmA = m0 + lrow; if (gmA >= M) gmA = M - 1;
    size_t aRow = (size_t)gmA * 32;
    size_t bRow = (size_t)(n0 + lrow) * 32;

#define ISSUE(ss) do {                                                         \
        int term_ = (ss) >> 3, kb_ = (ss) & 7;                                 \
        const uint4* A4_ = (term_ == 1) ? Alo : Ahi;                           \
        const uint4* W4_ = (term_ == 2) ? Wlo : Whi;                           \
        unsigned da = su32(&As[(ss) & (NSTG - 1)][lrow * SSTR + lc0 * 8]);     \
        unsigned db = su32(&Bs[(ss) & (NSTG - 1)][lrow * SSTR + lc0 * 8]);     \
        const uint4* sa = &A4_[aRow + kb_ * 4 + lc0];                          \
        const uint4* sb = &W4_[bRow + kb_ * 4 + lc0];                          \
        asm volatile("cp.async.cg.shared.global [%0], [%1], 16;" :: "r"(da), "l"(sa)); \
        asm volatile("cp.async.cg.shared.global [%0], [%1], 16;" :: "r"(da + 16), "l"(sa + 1)); \
        asm volatile("cp.async.cg.shared.global [%0], [%1], 16;" :: "r"(db), "l"(sb)); \
        asm volatile("cp.async.cg.shared.global [%0], [%1], 16;" :: "r"(db + 16), "l"(sb + 1)); \
        asm volatile("cp.async.commit_group;");                                \
    } while (0)

    ISSUE(0); ISSUE(1); ISSUE(2);

    int arow = wy * 32 + (lane & 15);
    int acol = (lane >> 4);
    int brow = wx * 64 + ((lane >> 4) & 1) * 8 + (lane & 7);
    int bcol = (lane >> 3) & 1;

    for (int c = 0; c < NCH; c++) {
        // wait for chunk c: allowed in-flight groups after it completes
        if (c <= NCH - 3)      asm volatile("cp.async.wait_group 2;");
        else if (c == NCH - 2) asm volatile("cp.async.wait_group 1;");
        else                   asm volatile("cp.async.wait_group 0;");
        __syncthreads();
        if (c + 3 < NCH) ISSUE(c + 3);

        int b = c & (NSTG - 1);
        const unsigned short* As_ = As[b];
        const unsigned short* Bs_ = Bs[b];
#pragma unroll
        for (int ks = 0; ks < 2; ks++) {
            unsigned af[2][4];
#pragma unroll
            for (int mt = 0; mt < 2; mt++) {
                unsigned addr = su32(&As_[(arow + mt * 16) * SSTR + (ks * 2 + acol) * 8]);
                asm volatile(
                    "ldmatrix.sync.aligned.m8n8.x4.shared.b16 {%0,%1,%2,%3}, [%4];"
                    : "=r"(af[mt][0]), "=r"(af[mt][1]), "=r"(af[mt][2]), "=r"(af[mt][3])
                    : "r"(addr));
            }
#pragma unroll
            for (int g = 0; g < 4; g++) {
                unsigned bf[4];
                unsigned addr = su32(&Bs_[(brow + g * 16) * SSTR + (ks * 2 + bcol) * 8]);
                asm volatile(
                    "ldmatrix.sync.aligned.m8n8.x4.shared.b16 {%0,%1,%2,%3}, [%4];"
                    : "=r"(bf[0]), "=r"(bf[1]), "=r"(bf[2]), "=r"(bf[3])
                    : "r"(addr));
#pragma unroll
                for (int mt = 0; mt < 2; mt++) {
                    asm volatile(
                        "mma.sync.aligned.m16n8k16.row.col.f32.bf16.bf16.f32 "
                        "{%0,%1,%2,%3}, {%4,%5,%6,%7}, {%8,%9}, {%0,%1,%2,%3};"
                        : "+f"(acc[mt][2 * g][0]), "+f"(acc[mt][2 * g][1]),
                          "+f"(acc[mt][2 * g][2]), "+f"(acc[mt][2 * g][3])
                        : "r"(af[mt][0]), "r"(af[mt][1]),
                          "r"(af[mt][2]), "r"(af[mt][3]),
                          "r"(bf[0]), "r"(bf[1]));
                    asm volatile(
                        "mma.sync.aligned.m16n8k16.row.col.f32.bf16.bf16.f32 "
                        "{%0,%1,%2,%3}, {%4,%5,%6,%7}, {%8,%9}, {%0,%1,%2,%3};"
                        : "+f"(acc[mt][2 * g + 1][0]), "+f"(acc[mt][2 * g + 1][1]),
                          "+f"(acc[mt][2 * g + 1][2]), "+f"(acc[mt][2 * g + 1][3])
                        : "r"(af[mt][0]), "r"(af[mt][1]),
                          "r"(af[mt][2]), "r"(af[mt][3]),
                          "r"(bf[2]), "r"(bf[3]));
                }
            }
        }
    }

    // epilogue
#pragma unroll
    for (int mt = 0; mt < 2; mt++) {
        int gm0 = m0 + wy * 32 + mt * 16 + grp;
#pragma unroll
        for (int nt = 0; nt < 8; nt++) {
            int nl = wx * 64 + nt * 8 + tig * 2;
            int gn = n0 + nl;
            float bx = bsm[nl], by = bsm[nl + 1];
            float v0 = acc[mt][nt][0] + bx;
            float v1 = acc[mt][nt][1] + by;
            float v2 = acc[mt][nt][2] + bx;
            float v3 = acc[mt][nt][3] + by;
            if (mode == 1) {
                v0 = fmaxf(v0, 0.f); v1 = fmaxf(v1, 0.f);
                v2 = fmaxf(v2, 0.f); v3 = fmaxf(v3, 0.f);
                unsigned short h0, l0, h1, l1;
                if (gm0 < M) {
                    f2bf2(v0, h0, l0); f2bf2(v1, h1, l1);
                    size_t idx = (size_t)gm0 * 128 + (gn >> 1);
                    outHi[idx] = (unsigned)h0 | ((unsigned)h1 << 16);
                    outLo[idx] = (unsigned)l0 | ((unsigned)l1 << 16);
                }
                if (gm0 + 8 < M) {
                    f2bf2(v2, h0, l0); f2bf2(v3, h1, l1);
                    size_t idx = (size_t)(gm0 + 8) * 128 + (gn >> 1);
                    outHi[idx] = (unsigned)h0 | ((unsigned)h1 << 16);
                    outLo[idx] = (unsigned)l0 | ((unsigned)l1 << 16);
                }
            } else if (n0 == 0) {
                // p region -> fp16
                if (gm0 < M)
                    *(__half2*)(outP + (size_t)gm0 * 128 + nl) = __floats2half2_rn(v0, v1);
                if (gm0 + 8 < M)
                    *(__half2*)(outP + (size_t)(gm0 + 8) * 128 + nl) = __floats2half2_rn(v2, v3);
            } else {
                // q region -> fp32
                if (gm0 < M)
                    *(float2*)(outQ + (size_t)gm0 * 128 + nl) = make_float2(v0, v1);
                if (gm0 + 8 < M)
                    *(float2*)(outQ + (size_t)(gm0 + 8) * 128 + nl) = make_float2(v2, v3);
            }
        }
    }
#undef ISSUE
}

// ---------------------------------------------------------------
// launch — inputs: x, Wl1, bl1, Wr1, Wl2, bl2, Wr2, edge_index
// ---------------------------------------------------------------
extern "C" void kernel_launch(void* const* d_in, const int* in_sizes, int n_in,
                              void* d_out, int out_size) {
    const float* x   = (const float*)d_in[0];
    const float* Wl1 = (const float*)d_in[1];
    const float* bl1 = (const float*)d_in[2];
    const float* Wr1 = (const float*)d_in[3];
    const float* Wl2 = (const float*)d_in[4];
    const float* bl2 = (const float*)d_in[5];
    const float* Wr2 = (const float*)d_in[6];
    const void*  ei  = d_in[7];
    float* out = (float*)d_out;

    unsigned *A1hi, *A1lo, *A2hi, *A2lo;
    unsigned short *W1hi, *W1lo, *W2hi, *W2lo;
    float *b1, *b2, *q;
    __half* p;
    cudaGetSymbolAddress((void**)&A1hi, g_A1hi);
    cudaGetSymbolAddress((void**)&A1lo, g_A1lo);
    cudaGetSymbolAddress((void**)&A2hi, g_A2hi);
    cudaGetSymbolAddress((void**)&A2lo, g_A2lo);
    cudaGetSymbolAddress((void**)&W1hi, g_W1hi);
    cudaGetSymbolAddress((void**)&W1lo, g_W1lo);
    cudaGetSymbolAddress((void**)&W2hi, g_W2hi);
    cudaGetSymbolAddress((void**)&W2lo, g_W2lo);
    cudaGetSymbolAddress((void**)&b1, g_b1);
    cudaGetSymbolAddress((void**)&b2, g_b2);
    cudaGetSymbolAddress((void**)&p, g_p);
    cudaGetSymbolAddress((void**)&q, g_q);

    // 0. init + decode edges + degree
    init_kernel<<<(N_NODES + 255) / 256, 256>>>((const int*)ei);
    convert_kernel<<<(2 * N_EDGES + 255) / 256, 256>>>(ei);

    // 1. CSR build
    scan_blocks_kernel<<<SCAN_NB, 256>>>();
    scan_tops_kernel<<<1, 256>>>();
    scan_finish_kernel<<<SCAN_NB, 256>>>();
    reorder_kernel<<<(N_EDGES + 255) / 256, 256>>>();

    // 2. weight/bias prep
    convW_kernel<<<(2 * 256 * 256 + 255) / 256, 256>>>(Wl1, Wr1, Wl2, Wr2, bl1, bl2);

    // 3. layer-1 gather + x conversion -> A1
    gather1_kernel<<<(N_NODES + 7) / 8, 256>>>(x);

    // 4. GEMM1: h = relu([mean|x]@[Wl1|Wr1]ᵀ + b1) -> A2 (bf16 split)
    {
        dim3 grid(2, GEMM_MB);
        gemm_mma_kernel<<<grid, 256>>>((const uint4*)A1hi, (const uint4*)A1lo,
                                       (const uint4*)W1hi, (const uint4*)W1lo,
                                       b1, nullptr, nullptr, A2hi, A2lo, N_NODES, 1);
    }

    // 5. GEMM2: p = h@Wl2ᵀ (fp16), q = h@Wr2ᵀ + bl2 (fp32)
    {
        dim3 grid(2, GEMM_MB);
        gemm_mma_kernel<<<grid, 256>>>((const uint4*)A2hi, (const uint4*)A2lo,
                                       (const uint4*)W2hi, (const uint4*)W2lo,
                                       b2, p, q, nullptr, nullptr, N_NODES, 0);
    }

    // 6. layer-2 gather on fp16 p, fused with final combine
    gather2_kernel<<<(N_NODES + 7) / 8, 256>>>(out);
}

// round 10
// speedup vs baseline: 2.9069x; 1.3385x over previous
#include <cuda_runtime.h>
#include <cuda_fp16.h>
#include <cstdint>
#include <cstddef>

#define N_NODES 50000
#define N_EDGES 800000
#define SCAN_NB ((N_NODES + 255) / 256)   // 196 blocks
#define GEMM_MB ((N_NODES + 127) / 128)   // 391 CTAs in M

// ---- device scratch ----
// A buffers: fp16 [M,256] packed as uints (row stride 128 uints)
// layout: uints 0..63 = mean part (128 fp16), uints 64..127 = x/h part
__device__ __align__(16) unsigned g_A1hi[(size_t)N_NODES * 128];
__device__ __align__(16) unsigned g_A1lo[(size_t)N_NODES * 128];
__device__ __align__(16) unsigned g_A2hi[(size_t)N_NODES * 128];
__device__ __align__(16) unsigned g_A2lo[(size_t)N_NODES * 128];
__device__ __align__(16) __half   g_p[(size_t)N_NODES * 128];    // p fp16
__device__ __align__(16) float    g_q[(size_t)N_NODES * 128];    // q fp32
__device__ __align__(16) unsigned short g_W1[256 * 256];         // fp16
__device__ __align__(16) unsigned short g_W2[256 * 256];         // fp16
__device__ __align__(16) float g_b1[256];
__device__ __align__(16) float g_b2[256];
__device__ __align__(16) float g_dinv[N_NODES];
__device__ __align__(16) int   g_eidx[2 * N_EDGES];
__device__ __align__(16) int   g_degi[N_NODES];
__device__ __align__(16) int   g_row[N_NODES + 1];
__device__ __align__(16) int   g_cur[N_NODES];
__device__ __align__(16) int   g_csrc[N_EDGES];
__device__ __align__(16) int   g_bsum[SCAN_NB];
__device__ __align__(16) int   g_boff[256];
__device__ int g_fmt;

// ---------------- helpers ----------------
// fp16 hi/lo split: v = hi + lo + O(2^-22)
__device__ __forceinline__ void f2h2(float v, unsigned short& h, unsigned short& l) {
    __half hh = __float2half_rn(v);
    float hf = __half2float(hh);
    __half hl = __float2half_rn(v - hf);
    h = *reinterpret_cast<unsigned short*>(&hh);
    l = *reinterpret_cast<unsigned short*>(&hl);
}

__device__ __forceinline__ unsigned su32(const void* p) {
    return (unsigned)__cvta_generic_to_shared(p);
}

// ---------------------------------------------------------------
// init (fused detect + degree zero)
// ---------------------------------------------------------------
__global__ void init_kernel(const int* __restrict__ ei32) {
    int i = blockIdx.x * blockDim.x + threadIdx.x;
    if (i < N_NODES) g_degi[i] = 0;
    if (i == 0) {
        int odd_nonzero = 0;
        for (int k = 0; k < 512; k++) odd_nonzero += (ei32[2 * k + 1] != 0);
        g_fmt = (odd_nonzero == 0) ? 1 : 0;
    }
}

__global__ void convert_kernel(const void* __restrict__ ei) {
    int i = blockIdx.x * blockDim.x + threadIdx.x;
    if (i >= 2 * N_EDGES) return;
    int v;
    if (g_fmt) v = (int)((const long long*)ei)[i];
    else       v = ((const int*)ei)[i];
    g_eidx[i] = v;
    if (i >= N_EDGES) atomicAdd(&g_degi[v], 1);
}

__global__ void scan_blocks_kernel() {
    __shared__ int s[256];
    int t = threadIdx.x;
    int i = blockIdx.x * 256 + t;
    int v = (i < N_NODES) ? g_degi[i] : 0;
    s[t] = v;
    __syncthreads();
#pragma unroll
    for (int off = 1; off < 256; off <<= 1) {
        int add = (t >= off) ? s[t - off] : 0;
        __syncthreads();
        s[t] += add;
        __syncthreads();
    }
    int incl = s[t];
    if (i < N_NODES) g_row[i] = incl - v;
    if (t == 255) g_bsum[blockIdx.x] = incl;
}

__global__ void scan_tops_kernel() {
    __shared__ int s[256];
    int t = threadIdx.x;
    int v = (t < SCAN_NB) ? g_bsum[t] : 0;
    s[t] = v;
    __syncthreads();
#pragma unroll
    for (int off = 1; off < 256; off <<= 1) {
        int add = (t >= off) ? s[t - off] : 0;
        __syncthreads();
        s[t] += add;
        __syncthreads();
    }
    if (t < SCAN_NB) g_boff[t] = s[t] - v;
}

__global__ void scan_finish_kernel() {
    int i = blockIdx.x * 256 + threadIdx.x;
    if (i < N_NODES) {
        int r = g_row[i] + g_boff[blockIdx.x];
        g_row[i] = r;
        g_cur[i] = r;
        g_dinv[i] = 1.0f / fmaxf((float)g_degi[i], 1.0f);
    }
    if (i == 0) g_row[N_NODES] = N_EDGES;
}

__global__ void reorder_kernel() {
    int e = blockIdx.x * blockDim.x + threadIdx.x;
    if (e >= N_EDGES) return;
    int d = g_eidx[N_EDGES + e];
    int pos = atomicAdd(&g_cur[d], 1);
    g_csrc[pos] = g_eidx[e];
}

// ---------------------------------------------------------------
// weight + bias prep: W1=[Wl1|Wr1], W2=[Wl2;Wr2] as fp16
// ---------------------------------------------------------------
__global__ void convW_kernel(const float* __restrict__ Wl1, const float* __restrict__ Wr1,
                             const float* __restrict__ Wl2, const float* __restrict__ Wr2,
                             const float* __restrict__ bl1, const float* __restrict__ bl2) {
    int i = blockIdx.x * blockDim.x + threadIdx.x;
    if (i < 2 * 256 * 256) {
        int op = i >> 16;
        int rem = i & 65535;
        int n = rem >> 8, k = rem & 255;
        float w;
        if (op == 0) w = (k < 128) ? Wl1[n * 128 + k] : Wr1[n * 128 + (k - 128)];
        else         w = (n < 128) ? Wl2[n * 256 + k] : Wr2[(n - 128) * 256 + k];
        __half hw = __float2half_rn(w);
        unsigned short hb = *reinterpret_cast<unsigned short*>(&hw);
        if (op == 0) g_W1[rem] = hb;
        else         g_W2[rem] = hb;
    }
    if (i < 256) g_b1[i] = bl1[i];
    else if (i < 512) {
        int n = i - 256;
        g_b2[n] = (n < 128) ? 0.0f : bl2[n - 128];
    }
}

// x -> A1 x-part (uints 64..127): fp16 hi/lo
__global__ void xconv_kernel(const float* __restrict__ x) {
    int i4 = blockIdx.x * blockDim.x + threadIdx.x;
    if (i4 >= N_NODES * 32) return;
    int m = i4 >> 5, c4 = i4 & 31;
    float4 v = ((const float4*)x)[i4];
    unsigned short h0, l0, h1, l1, h2, l2, h3, l3;
    f2h2(v.x, h0, l0); f2h2(v.y, h1, l1);
    f2h2(v.z, h2, l2); f2h2(v.w, h3, l3);
    size_t base = (size_t)m * 128 + 64 + c4 * 2;
    g_A1hi[base]     = (unsigned)h0 | ((unsigned)h1 << 16);
    g_A1hi[base + 1] = (unsigned)h2 | ((unsigned)h3 << 16);
    g_A1lo[base]     = (unsigned)l0 | ((unsigned)l1 << 16);
    g_A1lo[base + 1] = (unsigned)l2 | ((unsigned)l3 << 16);
}

// ---------------------------------------------------------------
// gather1: mean = (sum fp16 xh[neighbors]) * dinv -> A1 mean part
// reads the fp16 hi x-part written by xconv (must run after it)
// ---------------------------------------------------------------
__global__ void gather1_kernel() {
    int warp = (blockIdx.x * blockDim.x + threadIdx.x) >> 5;
    int lane = threadIdx.x & 31;
    if (warp >= N_NODES) return;
    int start = g_row[warp];
    int end = g_row[warp + 1];
    float a0 = 0.f, a1 = 0.f, a2 = 0.f, a3 = 0.f;
    for (int base = start; base < end; base += 32) {
        int mye = base + lane;
        int sidx = (mye < end) ? g_csrc[mye] : 0;
        int cnt = end - base; if (cnt > 32) cnt = 32;
#pragma unroll 4
        for (int j = 0; j < cnt; j++) {
            int s = __shfl_sync(0xffffffffu, sidx, j);
            uint2 v = __ldg((const uint2*)(g_A1hi + (size_t)s * 128 + 64) + lane);
            float2 f0 = __half22float2(*reinterpret_cast<__half2*>(&v.x));
            float2 f1 = __half22float2(*reinterpret_cast<__half2*>(&v.y));
            a0 += f0.x; a1 += f0.y; a2 += f1.x; a3 += f1.y;
        }
    }
    float sc = g_dinv[warp];
    a0 *= sc; a1 *= sc; a2 *= sc; a3 *= sc;
    unsigned short h0, l0, h1, l1, h2, l2, h3, l3;
    f2h2(a0, h0, l0); f2h2(a1, h1, l1);
    f2h2(a2, h2, l2); f2h2(a3, h3, l3);
    size_t base = (size_t)warp * 128 + lane * 2;
    g_A1hi[base]     = (unsigned)h0 | ((unsigned)h1 << 16);
    g_A1hi[base + 1] = (unsigned)h2 | ((unsigned)h3 << 16);
    g_A1lo[base]     = (unsigned)l0 | ((unsigned)l1 << 16);
    g_A1lo[base + 1] = (unsigned)l2 | ((unsigned)l3 << 16);
}

// ---------------------------------------------------------------
// gather2 + final: out[n] = (sum fp16 p[nb]) * dinv[n] + q[n]
// ---------------------------------------------------------------
__global__ void gather2_kernel(float* __restrict__ out) {
    int warp = (blockIdx.x * blockDim.x + threadIdx.x) >> 5;
    int lane = threadIdx.x & 31;
    if (warp >= N_NODES) return;
    int start = g_row[warp];
    int end = g_row[warp + 1];
    float a0 = 0.f, a1 = 0.f, a2 = 0.f, a3 = 0.f;
    for (int base = start; base < end; base += 32) {
        int mye = base + lane;
        int sidx = (mye < end) ? g_csrc[mye] : 0;
        int cnt = end - base; if (cnt > 32) cnt = 32;
#pragma unroll 4
        for (int j = 0; j < cnt; j++) {
            int s = __shfl_sync(0xffffffffu, sidx, j);
            uint2 v = __ldg((const uint2*)(g_p + (size_t)s * 128) + lane);
            float2 f0 = __half22float2(*reinterpret_cast<__half2*>(&v.x));
            float2 f1 = __half22float2(*reinterpret_cast<__half2*>(&v.y));
            a0 += f0.x; a1 += f0.y; a2 += f1.x; a3 += f1.y;
        }
    }
    float s = g_dinv[warp];
    float4 q = __ldg((const float4*)(g_q + (size_t)warp * 128) + lane);
    float4 o;
    o.x = a0 * s + q.x;
    o.y = a1 * s + q.y;
    o.z = a2 * s + q.z;
    o.w = a3 * s + q.w;
    ((float4*)(out + (size_t)warp * 128))[lane] = o;
}

// ---------------------------------------------------------------
// mma.sync fp16 GEMM, 4-stage cp.async + ldmatrix.
// C[M,256] = Ah@Wᵀ + Al@Wᵀ (+bias)   [2-term fp16 split]
// CTA 128x128, 8 warps (4M x 2N), warp 32x64, BK=32.
// mode 0: p fp16 (n0=0) / q fp32 (n0=128);  mode 1: ReLU->fp16 hi/lo.
// ---------------------------------------------------------------
#define SSTR 40   // smem row stride in halves
#define NCH 16    // k-chunks: 2 terms x 8
#define NSTG 4

__global__ void __launch_bounds__(256, 2) gemm_mma_kernel(
    const uint4* __restrict__ Ahi, const uint4* __restrict__ Alo,
    const uint4* __restrict__ W4,
    const float* __restrict__ bias,
    __half* __restrict__ outP, float* __restrict__ outQ,
    unsigned* __restrict__ outHi, unsigned* __restrict__ outLo,
    int M, int mode) {
    __shared__ __align__(16) unsigned short As[NSTG][128 * SSTR];
    __shared__ __align__(16) unsigned short Bs[NSTG][128 * SSTR];
    __shared__ float bsm[128];

    int tid = threadIdx.x;
    int wid = tid >> 5, lane = tid & 31;
    int wy = wid & 3, wx = wid >> 2;
    int tig = lane & 3, grp = lane >> 2;
    int m0 = blockIdx.y * 128;
    int n0 = blockIdx.x * 128;

    if (tid < 128) bsm[tid] = bias[n0 + tid];

    float acc[2][8][4];
#pragma unroll
    for (int a = 0; a < 2; a++)
#pragma unroll
        for (int b = 0; b < 8; b++)
#pragma unroll
            for (int c = 0; c < 4; c++) acc[a][b][c] = 0.f;

    int lrow = tid >> 1;
    int lc0 = (tid & 1) * 2;
    int gmA = m0 + lrow; if (gmA >= M) gmA = M - 1;
    size_t aRow = (size_t)gmA * 32;
    size_t bRow = (size_t)(n0 + lrow) * 32;

#define ISSUE(ss) do {                                                         \
        int term_ = (ss) >> 3, kb_ = (ss) & 7;                                 \
        const uint4* A4_ = term_ ? Alo : Ahi;                                  \
        unsigned da = su32(&As[(ss) & (NSTG - 1)][lrow * SSTR + lc0 * 8]);     \
        unsigned db = su32(&Bs[(ss) & (NSTG - 1)][lrow * SSTR + lc0 * 8]);     \
        const uint4* sa = &A4_[aRow + kb_ * 4 + lc0];                          \
        const uint4* sb = &W4[bRow + kb_ * 4 + lc0];                           \
        asm volatile("cp.async.cg.shared.global [%0], [%1], 16;" :: "r"(da), "l"(sa)); \
        asm volatile("cp.async.cg.shared.global [%0], [%1], 16;" :: "r"(da + 16), "l"(sa + 1)); \
        asm volatile("cp.async.cg.shared.global [%0], [%1], 16;" :: "r"(db), "l"(sb)); \
        asm volatile("cp.async.cg.shared.global [%0], [%1], 16;" :: "r"(db + 16), "l"(sb + 1)); \
        asm volatile("cp.async.commit_group;");                                \
    } while (0)

    ISSUE(0); ISSUE(1); ISSUE(2);

    int arow = wy * 32 + (lane & 15);
    int acol = (lane >> 4);
    int brow = wx * 64 + ((lane >> 4) & 1) * 8 + (lane & 7);
    int bcol = (lane >> 3) & 1;

    for (int c = 0; c < NCH; c++) {
        if (c <= NCH - 3)      asm volatile("cp.async.wait_group 2;");
        else if (c == NCH - 2) asm volatile("cp.async.wait_group 1;");
        else                   asm volatile("cp.async.wait_group 0;");
        __syncthreads();
        if (c + 3 < NCH) ISSUE(c + 3);

        int b = c & (NSTG - 1);
        const unsigned short* As_ = As[b];
        const unsigned short* Bs_ = Bs[b];
#pragma unroll
        for (int ks = 0; ks < 2; ks++) {
            unsigned af[2][4];
#pragma unroll
            for (int mt = 0; mt < 2; mt++) {
                unsigned addr = su32(&As_[(arow + mt * 16) * SSTR + (ks * 2 + acol) * 8]);
                asm volatile(
                    "ldmatrix.sync.aligned.m8n8.x4.shared.b16 {%0,%1,%2,%3}, [%4];"
                    : "=r"(af[mt][0]), "=r"(af[mt][1]), "=r"(af[mt][2]), "=r"(af[mt][3])
                    : "r"(addr));
            }
#pragma unroll
            for (int g = 0; g < 4; g++) {
                unsigned bf[4];
                unsigned addr = su32(&Bs_[(brow + g * 16) * SSTR + (ks * 2 + bcol) * 8]);
                asm volatile(
                    "ldmatrix.sync.aligned.m8n8.x4.shared.b16 {%0,%1,%2,%3}, [%4];"
                    : "=r"(bf[0]), "=r"(bf[1]), "=r"(bf[2]), "=r"(bf[3])
                    : "r"(addr));
#pragma unroll
                for (int mt = 0; mt < 2; mt++) {
                    asm volatile(
                        "mma.sync.aligned.m16n8k16.row.col.f32.f16.f16.f32 "
                        "{%0,%1,%2,%3}, {%4,%5,%6,%7}, {%8,%9}, {%0,%1,%2,%3};"
                        : "+f"(acc[mt][2 * g][0]), "+f"(acc[mt][2 * g][1]),
                          "+f"(acc[mt][2 * g][2]), "+f"(acc[mt][2 * g][3])
                        : "r"(af[mt][0]), "r"(af[mt][1]),
                          "r"(af[mt][2]), "r"(af[mt][3]),
                          "r"(bf[0]), "r"(bf[1]));
                    asm volatile(
                        "mma.sync.aligned.m16n8k16.row.col.f32.f16.f16.f32 "
                        "{%0,%1,%2,%3}, {%4,%5,%6,%7}, {%8,%9}, {%0,%1,%2,%3};"
                        : "+f"(acc[mt][2 * g + 1][0]), "+f"(acc[mt][2 * g + 1][1]),
                          "+f"(acc[mt][2 * g + 1][2]), "+f"(acc[mt][2 * g + 1][3])
                        : "r"(af[mt][0]), "r"(af[mt][1]),
                          "r"(af[mt][2]), "r"(af[mt][3]),
                          "r"(bf[2]), "r"(bf[3]));
                }
            }
        }
    }

    // epilogue
#pragma unroll
    for (int mt = 0; mt < 2; mt++) {
        int gm0 = m0 + wy * 32 + mt * 16 + grp;
#pragma unroll
        for (int nt = 0; nt < 8; nt++) {
            int nl = wx * 64 + nt * 8 + tig * 2;
            float bx = bsm[nl], by = bsm[nl + 1];
            float v0 = acc[mt][nt][0] + bx;
            float v1 = acc[mt][nt][1] + by;
            float v2 = acc[mt][nt][2] + bx;
            float v3 = acc[mt][nt][3] + by;
            if (mode == 1) {
                v0 = fmaxf(v0, 0.f); v1 = fmaxf(v1, 0.f);
                v2 = fmaxf(v2, 0.f); v3 = fmaxf(v3, 0.f);
                unsigned short h0, l0, h1, l1;
                if (gm0 < M) {
                    f2h2(v0, h0, l0); f2h2(v1, h1, l1);
                    size_t idx = (size_t)gm0 * 128 + (nl >> 1) + n0 / 2;
                    outHi[idx] = (unsigned)h0 | ((unsigned)h1 << 16);
                    outLo[idx] = (unsigned)l0 | ((unsigned)l1 << 16);
                }
                if (gm0 + 8 < M) {
                    f2h2(v2, h0, l0); f2h2(v3, h1, l1);
                    size_t idx = (size_t)(gm0 + 8) * 128 + (nl >> 1) + n0 / 2;
                    outHi[idx] = (unsigned)h0 | ((unsigned)h1 << 16);
                    outLo[idx] = (unsigned)l0 | ((unsigned)l1 << 16);
                }
            } else if (n0 == 0) {
                if (gm0 < M)
                    *(__half2*)(outP + (size_t)gm0 * 128 + nl) = __floats2half2_rn(v0, v1);
                if (gm0 + 8 < M)
                    *(__half2*)(outP + (size_t)(gm0 + 8) * 128 + nl) = __floats2half2_rn(v2, v3);
            } else {
                if (gm0 < M)
                    *(float2*)(outQ + (size_t)gm0 * 128 + nl) = make_float2(v0, v1);
                if (gm0 + 8 < M)
                    *(float2*)(outQ + (size_t)(gm0 + 8) * 128 + nl) = make_float2(v2, v3);
            }
        }
    }
#undef ISSUE
}

// ---------------------------------------------------------------
// launch — inputs: x, Wl1, bl1, Wr1, Wl2, bl2, Wr2, edge_index
// ---------------------------------------------------------------
extern "C" void kernel_launch(void* const* d_in, const int* in_sizes, int n_in,
                              void* d_out, int out_size) {
    const float* x   = (const float*)d_in[0];
    const float* Wl1 = (const float*)d_in[1];
    const float* bl1 = (const float*)d_in[2];
    const float* Wr1 = (const float*)d_in[3];
    const float* Wl2 = (const float*)d_in[4];
    const float* bl2 = (const float*)d_in[5];
    const float* Wr2 = (const float*)d_in[6];
    const void*  ei  = d_in[7];
    float* out = (float*)d_out;

    unsigned *A1hi, *A1lo, *A2hi, *A2lo;
    unsigned short *W1, *W2;
    float *b1, *b2, *q;
    __half* p;
    cudaGetSymbolAddress((void**)&A1hi, g_A1hi);
    cudaGetSymbolAddress((void**)&A1lo, g_A1lo);
    cudaGetSymbolAddress((void**)&A2hi, g_A2hi);
    cudaGetSymbolAddress((void**)&A2lo, g_A2lo);
    cudaGetSymbolAddress((void**)&W1, g_W1);
    cudaGetSymbolAddress((void**)&W2, g_W2);
    cudaGetSymbolAddress((void**)&b1, g_b1);
    cudaGetSymbolAddress((void**)&b2, g_b2);
    cudaGetSymbolAddress((void**)&p, g_p);
    cudaGetSymbolAddress((void**)&q, g_q);

    // 0. init + decode edges + degree
    init_kernel<<<(N_NODES + 255) / 256, 256>>>((const int*)ei);
    convert_kernel<<<(2 * N_EDGES + 255) / 256, 256>>>(ei);

    // 1. CSR build
    scan_blocks_kernel<<<SCAN_NB, 256>>>();
    scan_tops_kernel<<<1, 256>>>();
    scan_finish_kernel<<<SCAN_NB, 256>>>();
    reorder_kernel<<<(N_EDGES + 255) / 256, 256>>>();

    // 2. weight/bias prep + x fp16 split (x-part of A1)
    convW_kernel<<<(2 * 256 * 256 + 255) / 256, 256>>>(Wl1, Wr1, Wl2, Wr2, bl1, bl2);
    xconv_kernel<<<(N_NODES * 32 + 255) / 256, 256>>>(x);

    // 3. layer-1 gather (fp16 x) -> A1 mean part
    gather1_kernel<<<(N_NODES + 7) / 8, 256>>>();

    // 4. GEMM1: h = relu([mean|x]@[Wl1|Wr1]ᵀ + b1) -> A2 (fp16 split)
    {
        dim3 grid(2, GEMM_MB);
        gemm_mma_kernel<<<grid, 256>>>((const uint4*)A1hi, (const uint4*)A1lo,
                                       (const uint4*)W1, b1,
                                       nullptr, nullptr, A2hi, A2lo, N_NODES, 1);
    }

    // 5. GEMM2: p = h@Wl2ᵀ (fp16), q = h@Wr2ᵀ + bl2 (fp32)
    {
        dim3 grid(2, GEMM_MB);
        gemm_mma_kernel<<<grid, 256>>>((const uint4*)A2hi, (const uint4*)A2lo,
                                       (const uint4*)W2, b2,
                                       p, q, nullptr, nullptr, N_NODES, 0);
    }

    // 6. layer-2 gather on fp16 p, fused with final combine
    gather2_kernel<<<(N_NODES + 7) / 8, 256>>>(out);
}

// round 11
// speedup vs baseline: 3.0838x; 1.0609x over previous
#include <cuda_runtime.h>
#include <cuda_fp16.h>
#include <cstdint>
#include <cstddef>

#define N_NODES 50000
#define N_EDGES 800000
#define SCAN_NB ((N_NODES + 255) / 256)   // 196 blocks
#define GEMM_MB ((N_NODES + 127) / 128)   // 391 CTAs in M
#define XCONV_ITEMS (N_NODES * 32)

// ---- device scratch ----
// A buffers: fp16 [M,256] packed as uints (row stride 128 uints)
// layout: uints 0..63 = mean part (128 fp16), uints 64..127 = x/h part
__device__ __align__(16) unsigned g_A1hi[(size_t)N_NODES * 128];
__device__ __align__(16) unsigned g_A1lo[(size_t)N_NODES * 128];
__device__ __align__(16) unsigned g_A2hi[(size_t)N_NODES * 128];
__device__ __align__(16) unsigned g_A2lo[(size_t)N_NODES * 128];
__device__ __align__(16) __half   g_p[(size_t)N_NODES * 128];    // p fp16
__device__ __align__(16) float    g_q[(size_t)N_NODES * 128];    // q fp32
__device__ __align__(16) unsigned short g_W1[256 * 256];         // fp16
__device__ __align__(16) unsigned short g_W2[256 * 256];         // fp16
__device__ __align__(16) float g_b1[256];
__device__ __align__(16) float g_b2[256];
__device__ __align__(16) float g_dinv[N_NODES];
__device__ __align__(16) int   g_eidx[2 * N_EDGES];
__device__ __align__(16) int   g_degi[N_NODES];
__device__ __align__(16) int   g_row[N_NODES + 1];
__device__ __align__(16) int   g_cur[N_NODES];
__device__ __align__(16) int   g_csrc[N_EDGES];
__device__ __align__(16) int   g_bsum[SCAN_NB];
__device__ int g_fmt;

// ---------------- helpers ----------------
__device__ __forceinline__ void f2h2(float v, unsigned short& h, unsigned short& l) {
    __half hh = __float2half_rn(v);
    float hf = __half2float(hh);
    __half hl = __float2half_rn(v - hf);
    h = *reinterpret_cast<unsigned short*>(&hh);
    l = *reinterpret_cast<unsigned short*>(&hl);
}

__device__ __forceinline__ unsigned su32(const void* p) {
    return (unsigned)__cvta_generic_to_shared(p);
}

// ---------------------------------------------------------------
// init: zero degrees + parallel edge-format probe (block 0)
// ---------------------------------------------------------------
__global__ void init_kernel(const int* __restrict__ ei32) {
    int i = blockIdx.x * blockDim.x + threadIdx.x;
    if (i < N_NODES) g_degi[i] = 0;
    if (blockIdx.x == 0) {
        __shared__ int s_nz;
        if (threadIdx.x == 0) s_nz = 0;
        __syncthreads();
        int nz = 0;
        for (int k = threadIdx.x; k < 512; k += 256)
            nz |= (ei32[2 * k + 1] != 0);
        if (nz) atomicOr(&s_nz, 1);
        __syncthreads();
        if (threadIdx.x == 0) g_fmt = s_nz ? 0 : 1;
    }
}

__global__ void convert_kernel(const void* __restrict__ ei) {
    int i = blockIdx.x * blockDim.x + threadIdx.x;
    if (i >= 2 * N_EDGES) return;
    int v;
    if (g_fmt) v = (int)((const long long*)ei)[i];
    else       v = ((const int*)ei)[i];
    g_eidx[i] = v;
    if (i >= N_EDGES) atomicAdd(&g_degi[v], 1);
}

__global__ void scan_blocks_kernel() {
    __shared__ int s[256];
    int t = threadIdx.x;
    int i = blockIdx.x * 256 + t;
    int v = (i < N_NODES) ? g_degi[i] : 0;
    s[t] = v;
    __syncthreads();
#pragma unroll
    for (int off = 1; off < 256; off <<= 1) {
        int add = (t >= off) ? s[t - off] : 0;
        __syncthreads();
        s[t] += add;
        __syncthreads();
    }
    int incl = s[t];
    if (i < N_NODES) g_row[i] = incl - v;
    if (t == 255) g_bsum[blockIdx.x] = incl;
}

// scan_finish: block offset computed locally (no scan_tops launch)
__global__ void scan_finish_kernel() {
    __shared__ int red[256];
    int t = threadIdx.x;
    int partial = 0;
    for (int k = t; k < blockIdx.x; k += 256) partial += g_bsum[k];
    red[t] = partial;
    __syncthreads();
#pragma unroll
    for (int s = 128; s > 0; s >>= 1) {
        if (t < s) red[t] += red[t + s];
        __syncthreads();
    }
    int boff = red[0];
    int i = blockIdx.x * 256 + t;
    if (i < N_NODES) {
        int r = g_row[i] + boff;
        g_row[i] = r;
        g_cur[i] = r;
        g_dinv[i] = 1.0f / fmaxf((float)g_degi[i], 1.0f);
    }
    if (i == 0) g_row[N_NODES] = N_EDGES;
}

__global__ void reorder_kernel() {
    int e = blockIdx.x * blockDim.x + threadIdx.x;
    if (e >= N_EDGES) return;
    int d = g_eidx[N_EDGES + e];
    int pos = atomicAdd(&g_cur[d], 1);
    g_csrc[pos] = g_eidx[e];
}

// ---------------------------------------------------------------
// prep: fused x fp16-split + weight/bias conversion
// items [0, XCONV_ITEMS): x -> A1 x-part; rest: W1/W2/b1/b2
// ---------------------------------------------------------------
__global__ void prep_kernel(const float* __restrict__ x,
                            const float* __restrict__ Wl1, const float* __restrict__ Wr1,
                            const float* __restrict__ Wl2, const float* __restrict__ Wr2,
                            const float* __restrict__ bl1, const float* __restrict__ bl2) {
    int i = blockIdx.x * blockDim.x + threadIdx.x;
    if (i < XCONV_ITEMS) {
        int m = i >> 5, c4 = i & 31;
        float4 v = ((const float4*)x)[i];
        unsigned short h0, l0, h1, l1, h2, l2, h3, l3;
        f2h2(v.x, h0, l0); f2h2(v.y, h1, l1);
        f2h2(v.z, h2, l2); f2h2(v.w, h3, l3);
        size_t base = (size_t)m * 128 + 64 + c4 * 2;
        g_A1hi[base]     = (unsigned)h0 | ((unsigned)h1 << 16);
        g_A1hi[base + 1] = (unsigned)h2 | ((unsigned)h3 << 16);
        g_A1lo[base]     = (unsigned)l0 | ((unsigned)l1 << 16);
        g_A1lo[base + 1] = (unsigned)l2 | ((unsigned)l3 << 16);
        return;
    }
    int j = i - XCONV_ITEMS;
    if (j < 2 * 256 * 256) {
        int op = j >> 16;
        int rem = j & 65535;
        int n = rem >> 8, k = rem & 255;
        float w;
        if (op == 0) w = (k < 128) ? Wl1[n * 128 + k] : Wr1[n * 128 + (k - 128)];
        else         w = (n < 128) ? Wl2[n * 256 + k] : Wr2[(n - 128) * 256 + k];
        __half hw = __float2half_rn(w);
        unsigned short hb = *reinterpret_cast<unsigned short*>(&hw);
        if (op == 0) g_W1[rem] = hb;
        else         g_W2[rem] = hb;
        return;
    }
    j -= 2 * 256 * 256;
    if (j < 256) g_b1[j] = bl1[j];
    else if (j < 512) {
        int n = j - 256;
        g_b2[n] = (n < 128) ? 0.0f : bl2[n - 128];
    }
}

// ---------------------------------------------------------------
// gather1: mean = (sum fp16 xh[neighbors]) * dinv -> A1 mean part
// ---------------------------------------------------------------
__global__ void gather1_kernel() {
    int warp = (blockIdx.x * blockDim.x + threadIdx.x) >> 5;
    int lane = threadIdx.x & 31;
    if (warp >= N_NODES) return;
    int start = g_row[warp];
    int end = g_row[warp + 1];
    float a0 = 0.f, a1 = 0.f, a2 = 0.f, a3 = 0.f;
    for (int base = start; base < end; base += 32) {
        int mye = base + lane;
        int sidx = (mye < end) ? g_csrc[mye] : 0;
        int cnt = end - base; if (cnt > 32) cnt = 32;
#pragma unroll 4
        for (int j = 0; j < cnt; j++) {
            int s = __shfl_sync(0xffffffffu, sidx, j);
            uint2 v = __ldg((const uint2*)(g_A1hi + (size_t)s * 128 + 64) + lane);
            float2 f0 = __half22float2(*reinterpret_cast<__half2*>(&v.x));
            float2 f1 = __half22float2(*reinterpret_cast<__half2*>(&v.y));
            a0 += f0.x; a1 += f0.y; a2 += f1.x; a3 += f1.y;
        }
    }
    float sc = g_dinv[warp];
    a0 *= sc; a1 *= sc; a2 *= sc; a3 *= sc;
    unsigned short h0, l0, h1, l1, h2, l2, h3, l3;
    f2h2(a0, h0, l0); f2h2(a1, h1, l1);
    f2h2(a2, h2, l2); f2h2(a3, h3, l3);
    size_t base = (size_t)warp * 128 + lane * 2;
    g_A1hi[base]     = (unsigned)h0 | ((unsigned)h1 << 16);
    g_A1hi[base + 1] = (unsigned)h2 | ((unsigned)h3 << 16);
    g_A1lo[base]     = (unsigned)l0 | ((unsigned)l1 << 16);
    g_A1lo[base + 1] = (unsigned)l2 | ((unsigned)l3 << 16);
}

// ---------------------------------------------------------------
// gather2 + final: out[n] = (sum fp16 p[nb]) * dinv[n] + q[n]
// ---------------------------------------------------------------
__global__ void gather2_kernel(float* __restrict__ out) {
    int warp = (blockIdx.x * blockDim.x + threadIdx.x) >> 5;
    int lane = threadIdx.x & 31;
    if (warp >= N_NODES) return;
    int start = g_row[warp];
    int end = g_row[warp + 1];
    float a0 = 0.f, a1 = 0.f, a2 = 0.f, a3 = 0.f;
    for (int base = start; base < end; base += 32) {
        int mye = base + lane;
        int sidx = (mye < end) ? g_csrc[mye] : 0;
        int cnt = end - base; if (cnt > 32) cnt = 32;
#pragma unroll 4
        for (int j = 0; j < cnt; j++) {
            int s = __shfl_sync(0xffffffffu, sidx, j);
            uint2 v = __ldg((const uint2*)(g_p + (size_t)s * 128) + lane);
            float2 f0 = __half22float2(*reinterpret_cast<__half2*>(&v.x));
            float2 f1 = __half22float2(*reinterpret_cast<__half2*>(&v.y));
            a0 += f0.x; a1 += f0.y; a2 += f1.x; a3 += f1.y;
        }
    }
    float s = g_dinv[warp];
    float4 q = __ldg((const float4*)(g_q + (size_t)warp * 128) + lane);
    float4 o;
    o.x = a0 * s + q.x;
    o.y = a1 * s + q.y;
    o.z = a2 * s + q.z;
    o.w = a3 * s + q.w;
    ((float4*)(out + (size_t)warp * 128))[lane] = o;
}

// ---------------------------------------------------------------
// mma.sync fp16 GEMM, 4-stage cp.async + ldmatrix.
// C[M,256] = Ah@Wᵀ [+ Al@Wᵀ] (+bias)
// mode 1: 2 terms, ReLU -> fp16 hi/lo (h). mode 0: p-CTA (n0=0)
// 1 term -> fp16 p; q-CTA (n0=128) 2 terms -> fp32 q.
// ---------------------------------------------------------------
#define SSTR 40
#define NSTG 4

__global__ void __launch_bounds__(256, 2) gemm_mma_kernel(
    const uint4* __restrict__ Ahi, const uint4* __restrict__ Alo,
    const uint4* __restrict__ W4,
    const float* __restrict__ bias,
    __half* __restrict__ outP, float* __restrict__ outQ,
    unsigned* __restrict__ outHi, unsigned* __restrict__ outLo,
    int M, int mode) {
    __shared__ __align__(16) unsigned short As[NSTG][128 * SSTR];
    __shared__ __align__(16) unsigned short Bs[NSTG][128 * SSTR];
    __shared__ float bsm[128];

    int tid = threadIdx.x;
    int wid = tid >> 5, lane = tid & 31;
    int wy = wid & 3, wx = wid >> 2;
    int tig = lane & 3, grp = lane >> 2;
    int m0 = blockIdx.y * 128;
    int n0 = blockIdx.x * 128;

    int nch = (mode == 0 && n0 == 0) ? 8 : 16;   // p-half: single term

    if (tid < 128) bsm[tid] = bias[n0 + tid];

    float acc[2][8][4];
#pragma unroll
    for (int a = 0; a < 2; a++)
#pragma unroll
        for (int b = 0; b < 8; b++)
#pragma unroll
            for (int c = 0; c < 4; c++) acc[a][b][c] = 0.f;

    int lrow = tid >> 1;
    int lc0 = (tid & 1) * 2;
    int gmA = m0 + lrow; if (gmA >= M) gmA = M - 1;
    size_t aRow = (size_t)gmA * 32;
    size_t bRow = (size_t)(n0 + lrow) * 32;

#define ISSUE(ss) do {                                                         \
        int term_ = (ss) >> 3, kb_ = (ss) & 7;                                 \
        const uint4* A4_ = term_ ? Alo : Ahi;                                  \
        unsigned da = su32(&As[(ss) & (NSTG - 1)][lrow * SSTR + lc0 * 8]);     \
        unsigned db = su32(&Bs[(ss) & (NSTG - 1)][lrow * SSTR + lc0 * 8]);     \
        const uint4* sa = &A4_[aRow + kb_ * 4 + lc0];                          \
        const uint4* sb = &W4[bRow + kb_ * 4 + lc0];                           \
        asm volatile("cp.async.cg.shared.global [%0], [%1], 16;" :: "r"(da), "l"(sa)); \
        asm volatile("cp.async.cg.shared.global [%0], [%1], 16;" :: "r"(da + 16), "l"(sa + 1)); \
        asm volatile("cp.async.cg.shared.global [%0], [%1], 16;" :: "r"(db), "l"(sb)); \
        asm volatile("cp.async.cg.shared.global [%0], [%1], 16;" :: "r"(db + 16), "l"(sb + 1)); \
        asm volatile("cp.async.commit_group;");                                \
    } while (0)

    ISSUE(0); ISSUE(1); ISSUE(2);

    int arow = wy * 32 + (lane & 15);
    int acol = (lane >> 4);
    int brow = wx * 64 + ((lane >> 4) & 1) * 8 + (lane & 7);
    int bcol = (lane >> 3) & 1;

    for (int c = 0; c < nch; c++) {
        if (c <= nch - 3)      asm volatile("cp.async.wait_group 2;");
        else if (c == nch - 2) asm volatile("cp.async.wait_group 1;");
        else                   asm volatile("cp.async.wait_group 0;");
        __syncthreads();
        if (c + 3 < nch) ISSUE(c + 3);

        int b = c & (NSTG - 1);
        const unsigned short* As_ = As[b];
        const unsigned short* Bs_ = Bs[b];
#pragma unroll
        for (int ks = 0; ks < 2; ks++) {
            unsigned af[2][4];
#pragma unroll
            for (int mt = 0; mt < 2; mt++) {
                unsigned addr = su32(&As_[(arow + mt * 16) * SSTR + (ks * 2 + acol) * 8]);
                asm volatile(
                    "ldmatrix.sync.aligned.m8n8.x4.shared.b16 {%0,%1,%2,%3}, [%4];"
                    : "=r"(af[mt][0]), "=r"(af[mt][1]), "=r"(af[mt][2]), "=r"(af[mt][3])
                    : "r"(addr));
            }
#pragma unroll
            for (int g = 0; g < 4; g++) {
                unsigned bf[4];
                unsigned addr = su32(&Bs_[(brow + g * 16) * SSTR + (ks * 2 + bcol) * 8]);
                asm volatile(
                    "ldmatrix.sync.aligned.m8n8.x4.shared.b16 {%0,%1,%2,%3}, [%4];"
                    : "=r"(bf[0]), "=r"(bf[1]), "=r"(bf[2]), "=r"(bf[3])
                    : "r"(addr));
#pragma unroll
                for (int mt = 0; mt < 2; mt++) {
                    asm volatile(
                        "mma.sync.aligned.m16n8k16.row.col.f32.f16.f16.f32 "
                        "{%0,%1,%2,%3}, {%4,%5,%6,%7}, {%8,%9}, {%0,%1,%2,%3};"
                        : "+f"(acc[mt][2 * g][0]), "+f"(acc[mt][2 * g][1]),
                          "+f"(acc[mt][2 * g][2]), "+f"(acc[mt][2 * g][3])
                        : "r"(af[mt][0]), "r"(af[mt][1]),
                          "r"(af[mt][2]), "r"(af[mt][3]),
                          "r"(bf[0]), "r"(bf[1]));
                    asm volatile(
                        "mma.sync.aligned.m16n8k16.row.col.f32.f16.f16.f32 "
                        "{%0,%1,%2,%3}, {%4,%5,%6,%7}, {%8,%9}, {%0,%1,%2,%3};"
                        : "+f"(acc[mt][2 * g + 1][0]), "+f"(acc[mt][2 * g + 1][1]),
                          "+f"(acc[mt][2 * g + 1][2]), "+f"(acc[mt][2 * g + 1][3])
                        : "r"(af[mt][0]), "r"(af[mt][1]),
                          "r"(af[mt][2]), "r"(af[mt][3]),
                          "r"(bf[2]), "r"(bf[3]));
                }
            }
        }
    }

    // epilogue
#pragma unroll
    for (int mt = 0; mt < 2; mt++) {
        int gm0 = m0 + wy * 32 + mt * 16 + grp;
#pragma unroll
        for (int nt = 0; nt < 8; nt++) {
            int nl = wx * 64 + nt * 8 + tig * 2;
            float bx = bsm[nl], by = bsm[nl + 1];
            float v0 = acc[mt][nt][0] + bx;
            float v1 = acc[mt][nt][1] + by;
            float v2 = acc[mt][nt][2] + bx;
            float v3 = acc[mt][nt][3] + by;
            if (mode == 1) {
                v0 = fmaxf(v0, 0.f); v1 = fmaxf(v1, 0.f);
                v2 = fmaxf(v2, 0.f); v3 = fmaxf(v3, 0.f);
                unsigned short h0, l0, h1, l1;
                if (gm0 < M) {
                    f2h2(v0, h0, l0); f2h2(v1, h1, l1);
                    size_t idx = (size_t)gm0 * 128 + (nl >> 1) + n0 / 2;
                    outHi[idx] = (unsigned)h0 | ((unsigned)h1 << 16);
                    outLo[idx] = (unsigned)l0 | ((unsigned)l1 << 16);
                }
                if (gm0 + 8 < M) {
                    f2h2(v2, h0, l0); f2h2(v3, h1, l1);
                    size_t idx = (size_t)(gm0 + 8) * 128 + (nl >> 1) + n0 / 2;
                    outHi[idx] = (unsigned)h0 | ((unsigned)h1 << 16);
                    outLo[idx] = (unsigned)l0 | ((unsigned)l1 << 16);
                }
            } else if (n0 == 0) {
                if (gm0 < M)
                    *(__half2*)(outP + (size_t)gm0 * 128 + nl) = __floats2half2_rn(v0, v1);
                if (gm0 + 8 < M)
                    *(__half2*)(outP + (size_t)(gm0 + 8) * 128 + nl) = __floats2half2_rn(v2, v3);
            } else {
                if (gm0 < M)
                    *(float2*)(outQ + (size_t)gm0 * 128 + nl) = make_float2(v0, v1);
                if (gm0 + 8 < M)
                    *(float2*)(outQ + (size_t)(gm0 + 8) * 128 + nl) = make_float2(v2, v3);
            }
        }
    }
#undef ISSUE
}

// ---------------------------------------------------------------
// launch — inputs: x, Wl1, bl1, Wr1, Wl2, bl2, Wr2, edge_index
// ---------------------------------------------------------------
extern "C" void kernel_launch(void* const* d_in, const int* in_sizes, int n_in,
                              void* d_out, int out_size) {
    const float* x   = (const float*)d_in[0];
    const float* Wl1 = (const float*)d_in[1];
    const float* bl1 = (const float*)d_in[2];
    const float* Wr1 = (const float*)d_in[3];
    const float* Wl2 = (const float*)d_in[4];
    const float* bl2 = (const float*)d_in[5];
    const float* Wr2 = (const float*)d_in[6];
    const void*  ei  = d_in[7];
    float* out = (float*)d_out;

    unsigned *A1hi, *A1lo, *A2hi, *A2lo;
    unsigned short *W1, *W2;
    float *b1, *b2, *q;
    __half* p;
    cudaGetSymbolAddress((void**)&A1hi, g_A1hi);
    cudaGetSymbolAddress((void**)&A1lo, g_A1lo);
    cudaGetSymbolAddress((void**)&A2hi, g_A2hi);
    cudaGetSymbolAddress((void**)&A2lo, g_A2lo);
    cudaGetSymbolAddress((void**)&W1, g_W1);
    cudaGetSymbolAddress((void**)&W2, g_W2);
    cudaGetSymbolAddress((void**)&b1, g_b1);
    cudaGetSymbolAddress((void**)&b2, g_b2);
    cudaGetSymbolAddress((void**)&p, g_p);
    cudaGetSymbolAddress((void**)&q, g_q);

    // 0. init (degrees + format probe) + edge decode/degree count
    init_kernel<<<(N_NODES + 255) / 256, 256>>>((const int*)ei);
    convert_kernel<<<(2 * N_EDGES + 255) / 256, 256>>>(ei);

    // 1. CSR build (2-pass scan) + reorder
    scan_blocks_kernel<<<SCAN_NB, 256>>>();
    scan_finish_kernel<<<SCAN_NB, 256>>>();
    reorder_kernel<<<(N_EDGES + 255) / 256, 256>>>();

    // 2. fused prep: x fp16 split + weights/biases
    {
        int items = XCONV_ITEMS + 2 * 256 * 256 + 512;
        prep_kernel<<<(items + 255) / 256, 256>>>(x, Wl1, Wr1, Wl2, Wr2, bl1, bl2);
    }

    // 3. layer-1 gather (fp16 x) -> A1 mean part
    gather1_kernel<<<(N_NODES + 7) / 8, 256>>>();

    // 4. GEMM1: h = relu([mean|x]@[Wl1|Wr1]ᵀ + b1) -> A2 (fp16 split)
    {
        dim3 grid(2, GEMM_MB);
        gemm_mma_kernel<<<grid, 256>>>((const uint4*)A1hi, (const uint4*)A1lo,
                                       (const uint4*)W1, b1,
                                       nullptr, nullptr, A2hi, A2lo, N_NODES, 1);
    }

    // 5. GEMM2: p = hi(h)@Wl2ᵀ (fp16, 1 term), q = h@Wr2ᵀ + bl2 (fp32, 2 terms)
    {
        dim3 grid(2, GEMM_MB);
        gemm_mma_kernel<<<grid, 256>>>((const uint4*)A2hi, (const uint4*)A2lo,
                                       (const uint4*)W2, b2,
                                       p, q, nullptr, nullptr, N_NODES, 0);
    }

    // 6. layer-2 gather on fp16 p, fused with final combine
    gather2_kernel<<<(N_NODES + 7) / 8, 256>>>(out);
}

// round 12
// speedup vs baseline: 3.5774x; 1.1600x over previous
#include <cuda_runtime.h>
#include <cuda_fp16.h>
#include <cstdint>
#include <cstddef>

#define N_NODES 50000
#define N_EDGES 800000
#define SCAN_NB ((N_NODES + 255) / 256)   // 196 blocks
#define GEMM_MB ((N_NODES + 127) / 128)   // 391 CTAs in M
#define XCONV_ITEMS (N_NODES * 32)

// ---- device scratch ----
// A1: fp16 [M,256] packed as uints (row stride 128 uints), hi only
// layout: uints 0..63 = mean part (128 fp16), uints 64..127 = x part
__device__ __align__(16) unsigned g_A1hi[(size_t)N_NODES * 128];
// A2 (h): hi/lo split — q path needs the 2-term accuracy
__device__ __align__(16) unsigned g_A2hi[(size_t)N_NODES * 128];
__device__ __align__(16) unsigned g_A2lo[(size_t)N_NODES * 128];
__device__ __align__(16) __half   g_p[(size_t)N_NODES * 128];    // p fp16
__device__ __align__(16) float    g_q[(size_t)N_NODES * 128];    // q fp32
__device__ __align__(16) unsigned short g_W1[256 * 256];         // fp16
__device__ __align__(16) unsigned short g_W2[256 * 256];         // fp16
__device__ __align__(16) float g_b1[256];
__device__ __align__(16) float g_b2[256];
__device__ __align__(16) float g_dinv[N_NODES];
__device__ __align__(16) int   g_eidx[2 * N_EDGES];
__device__ __align__(16) int   g_degi[N_NODES];
__device__ __align__(16) int   g_row[N_NODES + 1];
__device__ __align__(16) int   g_cur[N_NODES];
__device__ __align__(16) int   g_csrc[N_EDGES];
__device__ __align__(16) int   g_bsum[SCAN_NB];
__device__ int g_fmt;

// ---------------- helpers ----------------
__device__ __forceinline__ void f2h2(float v, unsigned short& h, unsigned short& l) {
    __half hh = __float2half_rn(v);
    float hf = __half2float(hh);
    __half hl = __float2half_rn(v - hf);
    h = *reinterpret_cast<unsigned short*>(&hh);
    l = *reinterpret_cast<unsigned short*>(&hl);
}

__device__ __forceinline__ unsigned su32(const void* p) {
    return (unsigned)__cvta_generic_to_shared(p);
}

// ---------------------------------------------------------------
// init: zero degrees + parallel edge-format probe (block 0)
// ---------------------------------------------------------------
__global__ void init_kernel(const int* __restrict__ ei32) {
    int i = blockIdx.x * blockDim.x + threadIdx.x;
    if (i < N_NODES) g_degi[i] = 0;
    if (blockIdx.x == 0) {
        __shared__ int s_nz;
        if (threadIdx.x == 0) s_nz = 0;
        __syncthreads();
        int nz = 0;
        for (int k = threadIdx.x; k < 512; k += 256)
            nz |= (ei32[2 * k + 1] != 0);
        if (nz) atomicOr(&s_nz, 1);
        __syncthreads();
        if (threadIdx.x == 0) g_fmt = s_nz ? 0 : 1;
    }
}

__global__ void convert_kernel(const void* __restrict__ ei) {
    int i = blockIdx.x * blockDim.x + threadIdx.x;
    if (i >= 2 * N_EDGES) return;
    int v;
    if (g_fmt) v = (int)((const long long*)ei)[i];
    else       v = ((const int*)ei)[i];
    g_eidx[i] = v;
    if (i >= N_EDGES) atomicAdd(&g_degi[v], 1);
}

__global__ void scan_blocks_kernel() {
    __shared__ int s[256];
    int t = threadIdx.x;
    int i = blockIdx.x * 256 + t;
    int v = (i < N_NODES) ? g_degi[i] : 0;
    s[t] = v;
    __syncthreads();
#pragma unroll
    for (int off = 1; off < 256; off <<= 1) {
        int add = (t >= off) ? s[t - off] : 0;
        __syncthreads();
        s[t] += add;
        __syncthreads();
    }
    int incl = s[t];
    if (i < N_NODES) g_row[i] = incl - v;
    if (t == 255) g_bsum[blockIdx.x] = incl;
}

__global__ void scan_finish_kernel() {
    __shared__ int red[256];
    int t = threadIdx.x;
    int partial = 0;
    for (int k = t; k < blockIdx.x; k += 256) partial += g_bsum[k];
    red[t] = partial;
    __syncthreads();
#pragma unroll
    for (int s = 128; s > 0; s >>= 1) {
        if (t < s) red[t] += red[t + s];
        __syncthreads();
    }
    int boff = red[0];
    int i = blockIdx.x * 256 + t;
    if (i < N_NODES) {
        int r = g_row[i] + boff;
        g_row[i] = r;
        g_cur[i] = r;
        g_dinv[i] = 1.0f / fmaxf((float)g_degi[i], 1.0f);
    }
    if (i == 0) g_row[N_NODES] = N_EDGES;
}

__global__ void reorder_kernel() {
    int e = blockIdx.x * blockDim.x + threadIdx.x;
    if (e >= N_EDGES) return;
    int d = g_eidx[N_EDGES + e];
    int pos = atomicAdd(&g_cur[d], 1);
    g_csrc[pos] = g_eidx[e];
}

// ---------------------------------------------------------------
// prep: fused x fp16 conversion (hi only) + weight/bias conversion
// ---------------------------------------------------------------
__global__ void prep_kernel(const float* __restrict__ x,
                            const float* __restrict__ Wl1, const float* __restrict__ Wr1,
                            const float* __restrict__ Wl2, const float* __restrict__ Wr2,
                            const float* __restrict__ bl1, const float* __restrict__ bl2) {
    int i = blockIdx.x * blockDim.x + threadIdx.x;
    if (i < XCONV_ITEMS) {
        int m = i >> 5, c4 = i & 31;
        float4 v = ((const float4*)x)[i];
        __half2 p0 = __floats2half2_rn(v.x, v.y);
        __half2 p1 = __floats2half2_rn(v.z, v.w);
        size_t base = (size_t)m * 128 + 64 + c4 * 2;
        g_A1hi[base]     = *reinterpret_cast<unsigned*>(&p0);
        g_A1hi[base + 1] = *reinterpret_cast<unsigned*>(&p1);
        return;
    }
    int j = i - XCONV_ITEMS;
    if (j < 2 * 256 * 256) {
        int op = j >> 16;
        int rem = j & 65535;
        int n = rem >> 8, k = rem & 255;
        float w;
        if (op == 0) w = (k < 128) ? Wl1[n * 128 + k] : Wr1[n * 128 + (k - 128)];
        else         w = (n < 128) ? Wl2[n * 256 + k] : Wr2[(n - 128) * 256 + k];
        __half hw = __float2half_rn(w);
        unsigned short hb = *reinterpret_cast<unsigned short*>(&hw);
        if (op == 0) g_W1[rem] = hb;
        else         g_W2[rem] = hb;
        return;
    }
    j -= 2 * 256 * 256;
    if (j < 256) g_b1[j] = bl1[j];
    else if (j < 512) {
        int n = j - 256;
        g_b2[n] = (n < 128) ? 0.0f : bl2[n - 128];
    }
}

// ---------------------------------------------------------------
// gather1: mean = (sum fp16 xh[neighbors]) * dinv -> A1 mean part (hi only)
// ---------------------------------------------------------------
__global__ void gather1_kernel() {
    int warp = (blockIdx.x * blockDim.x + threadIdx.x) >> 5;
    int lane = threadIdx.x & 31;
    if (warp >= N_NODES) return;
    int start = g_row[warp];
    int end = g_row[warp + 1];
    float a0 = 0.f, a1 = 0.f, a2 = 0.f, a3 = 0.f;
    for (int base = start; base < end; base += 32) {
        int mye = base + lane;
        int sidx = (mye < end) ? g_csrc[mye] : 0;
        int cnt = end - base; if (cnt > 32) cnt = 32;
#pragma unroll 4
        for (int j = 0; j < cnt; j++) {
            int s = __shfl_sync(0xffffffffu, sidx, j);
            uint2 v = __ldg((const uint2*)(g_A1hi + (size_t)s * 128 + 64) + lane);
            float2 f0 = __half22float2(*reinterpret_cast<__half2*>(&v.x));
            float2 f1 = __half22float2(*reinterpret_cast<__half2*>(&v.y));
            a0 += f0.x; a1 += f0.y; a2 += f1.x; a3 += f1.y;
        }
    }
    float sc = g_dinv[warp];
    __half2 p0 = __floats2half2_rn(a0 * sc, a1 * sc);
    __half2 p1 = __floats2half2_rn(a2 * sc, a3 * sc);
    size_t base = (size_t)warp * 128 + lane * 2;
    g_A1hi[base]     = *reinterpret_cast<unsigned*>(&p0);
    g_A1hi[base + 1] = *reinterpret_cast<unsigned*>(&p1);
}

// ---------------------------------------------------------------
// gather2 + final: out[n] = (sum fp16 p[nb]) * dinv[n] + q[n]
// ---------------------------------------------------------------
__global__ void gather2_kernel(float* __restrict__ out) {
    int warp = (blockIdx.x * blockDim.x + threadIdx.x) >> 5;
    int lane = threadIdx.x & 31;
    if (warp >= N_NODES) return;
    int start = g_row[warp];
    int end = g_row[warp + 1];
    float a0 = 0.f, a1 = 0.f, a2 = 0.f, a3 = 0.f;
    for (int base = start; base < end; base += 32) {
        int mye = base + lane;
        int sidx = (mye < end) ? g_csrc[mye] : 0;
        int cnt = end - base; if (cnt > 32) cnt = 32;
#pragma unroll 4
        for (int j = 0; j < cnt; j++) {
            int s = __shfl_sync(0xffffffffu, sidx, j);
            uint2 v = __ldg((const uint2*)(g_p + (size_t)s * 128) + lane);
            float2 f0 = __half22float2(*reinterpret_cast<__half2*>(&v.x));
            float2 f1 = __half22float2(*reinterpret_cast<__half2*>(&v.y));
            a0 += f0.x; a1 += f0.y; a2 += f1.x; a3 += f1.y;
        }
    }
    float s = g_dinv[warp];
    float4 q = __ldg((const float4*)(g_q + (size_t)warp * 128) + lane);
    float4 o;
    o.x = a0 * s + q.x;
    o.y = a1 * s + q.y;
    o.z = a2 * s + q.z;
    o.w = a3 * s + q.w;
    ((float4*)(out + (size_t)warp * 128))[lane] = o;
}

// ---------------------------------------------------------------
// mma.sync fp16 GEMM, 4-stage cp.async + ldmatrix.
// mode 1 (GEMM1): 1 term (Ahi only), ReLU -> fp16 hi/lo h.
// mode 0 (GEMM2): p-CTA (n0=0) 1 term -> fp16 p;
//                 q-CTA (n0=128) 2 terms -> fp32 q.
// ---------------------------------------------------------------
#define SSTR 40
#define NSTG 4

__global__ void __launch_bounds__(256, 2) gemm_mma_kernel(
    const uint4* __restrict__ Ahi, const uint4* __restrict__ Alo,
    const uint4* __restrict__ W4,
    const float* __restrict__ bias,
    __half* __restrict__ outP, float* __restrict__ outQ,
    unsigned* __restrict__ outHi, unsigned* __restrict__ outLo,
    int M, int mode) {
    __shared__ __align__(16) unsigned short As[NSTG][128 * SSTR];
    __shared__ __align__(16) unsigned short Bs[NSTG][128 * SSTR];
    __shared__ float bsm[128];

    int tid = threadIdx.x;
    int wid = tid >> 5, lane = tid & 31;
    int wy = wid & 3, wx = wid >> 2;
    int tig = lane & 3, grp = lane >> 2;
    int m0 = blockIdx.y * 128;
    int n0 = blockIdx.x * 128;

    // chunk count: 2 terms only for q-CTAs of GEMM2
    int nch = (mode == 0 && n0 == 128) ? 16 : 8;

    if (tid < 128) bsm[tid] = bias[n0 + tid];

    float acc[2][8][4];
#pragma unroll
    for (int a = 0; a < 2; a++)
#pragma unroll
        for (int b = 0; b < 8; b++)
#pragma unroll
            for (int c = 0; c < 4; c++) acc[a][b][c] = 0.f;

    int lrow = tid >> 1;
    int lc0 = (tid & 1) * 2;
    int gmA = m0 + lrow; if (gmA >= M) gmA = M - 1;
    size_t aRow = (size_t)gmA * 32;
    size_t bRow = (size_t)(n0 + lrow) * 32;

#define ISSUE(ss) do {                                                         \
        int term_ = (ss) >> 3, kb_ = (ss) & 7;                                 \
        const uint4* A4_ = term_ ? Alo : Ahi;                                  \
        unsigned da = su32(&As[(ss) & (NSTG - 1)][lrow * SSTR + lc0 * 8]);     \
        unsigned db = su32(&Bs[(ss) & (NSTG - 1)][lrow * SSTR + lc0 * 8]);     \
        const uint4* sa = &A4_[aRow + kb_ * 4 + lc0];                          \
        const uint4* sb = &W4[bRow + kb_ * 4 + lc0];                           \
        asm volatile("cp.async.cg.shared.global [%0], [%1], 16;" :: "r"(da), "l"(sa)); \
        asm volatile("cp.async.cg.shared.global [%0], [%1], 16;" :: "r"(da + 16), "l"(sa + 1)); \
        asm volatile("cp.async.cg.shared.global [%0], [%1], 16;" :: "r"(db), "l"(sb)); \
        asm volatile("cp.async.cg.shared.global [%0], [%1], 16;" :: "r"(db + 16), "l"(sb + 1)); \
        asm volatile("cp.async.commit_group;");                                \
    } while (0)

    ISSUE(0); ISSUE(1); ISSUE(2);

    int arow = wy * 32 + (lane & 15);
    int acol = (lane >> 4);
    int brow = wx * 64 + ((lane >> 4) & 1) * 8 + (lane & 7);
    int bcol = (lane >> 3) & 1;

    for (int c = 0; c < nch; c++) {
        if (c <= nch - 3)      asm volatile("cp.async.wait_group 2;");
        else if (c == nch - 2) asm volatile("cp.async.wait_group 1;");
        else                   asm volatile("cp.async.wait_group 0;");
        __syncthreads();
        if (c + 3 < nch) ISSUE(c + 3);

        int b = c & (NSTG - 1);
        const unsigned short* As_ = As[b];
        const unsigned short* Bs_ = Bs[b];
#pragma unroll
        for (int ks = 0; ks < 2; ks++) {
            unsigned af[2][4];
#pragma unroll
            for (int mt = 0; mt < 2; mt++) {
                unsigned addr = su32(&As_[(arow + mt * 16) * SSTR + (ks * 2 + acol) * 8]);
                asm volatile(
                    "ldmatrix.sync.aligned.m8n8.x4.shared.b16 {%0,%1,%2,%3}, [%4];"
                    : "=r"(af[mt][0]), "=r"(af[mt][1]), "=r"(af[mt][2]), "=r"(af[mt][3])
                    : "r"(addr));
            }
#pragma unroll
            for (int g = 0; g < 4; g++) {
                unsigned bf[4];
                unsigned addr = su32(&Bs_[(brow + g * 16) * SSTR + (ks * 2 + bcol) * 8]);
                asm volatile(
                    "ldmatrix.sync.aligned.m8n8.x4.shared.b16 {%0,%1,%2,%3}, [%4];"
                    : "=r"(bf[0]), "=r"(bf[1]), "=r"(bf[2]), "=r"(bf[3])
                    : "r"(addr));
#pragma unroll
                for (int mt = 0; mt < 2; mt++) {
                    asm volatile(
                        "mma.sync.aligned.m16n8k16.row.col.f32.f16.f16.f32 "
                        "{%0,%1,%2,%3}, {%4,%5,%6,%7}, {%8,%9}, {%0,%1,%2,%3};"
                        : "+f"(acc[mt][2 * g][0]), "+f"(acc[mt][2 * g][1]),
                          "+f"(acc[mt][2 * g][2]), "+f"(acc[mt][2 * g][3])
                        : "r"(af[mt][0]), "r"(af[mt][1]),
                          "r"(af[mt][2]), "r"(af[mt][3]),
                          "r"(bf[0]), "r"(bf[1]));
                    asm volatile(
                        "mma.sync.aligned.m16n8k16.row.col.f32.f16.f16.f32 "
                        "{%0,%1,%2,%3}, {%4,%5,%6,%7}, {%8,%9}, {%0,%1,%2,%3};"
                        : "+f"(acc[mt][2 * g + 1][0]), "+f"(acc[mt][2 * g + 1][1]),
                          "+f"(acc[mt][2 * g + 1][2]), "+f"(acc[mt][2 * g + 1][3])
                        : "r"(af[mt][0]), "r"(af[mt][1]),
                          "r"(af[mt][2]), "r"(af[mt][3]),
                          "r"(bf[2]), "r"(bf[3]));
                }
            }
        }
    }

    // epilogue
#pragma unroll
    for (int mt = 0; mt < 2; mt++) {
        int gm0 = m0 + wy * 32 + mt * 16 + grp;
#pragma unroll
        for (int nt = 0; nt < 8; nt++) {
            int nl = wx * 64 + nt * 8 + tig * 2;
            float bx = bsm[nl], by = bsm[nl + 1];
            float v0 = acc[mt][nt][0] + bx;
            float v1 = acc[mt][nt][1] + by;
            float v2 = acc[mt][nt][2] + bx;
            float v3 = acc[mt][nt][3] + by;
            if (mode == 1) {
                v0 = fmaxf(v0, 0.f); v1 = fmaxf(v1, 0.f);
                v2 = fmaxf(v2, 0.f); v3 = fmaxf(v3, 0.f);
                unsigned short h0, l0, h1, l1;
                if (gm0 < M) {
                    f2h2(v0, h0, l0); f2h2(v1, h1, l1);
                    size_t idx = (size_t)gm0 * 128 + (nl >> 1) + n0 / 2;
                    outHi[idx] = (unsigned)h0 | ((unsigned)h1 << 16);
                    outLo[idx] = (unsigned)l0 | ((unsigned)l1 << 16);
                }
                if (gm0 + 8 < M) {
                    f2h2(v2, h0, l0); f2h2(v3, h1, l1);
                    size_t idx = (size_t)(gm0 + 8) * 128 + (nl >> 1) + n0 / 2;
                    outHi[idx] = (unsigned)h0 | ((unsigned)h1 << 16);
                    outLo[idx] = (unsigned)l0 | ((unsigned)l1 << 16);
                }
            } else if (n0 == 0) {
                if (gm0 < M)
                    *(__half2*)(outP + (size_t)gm0 * 128 + nl) = __floats2half2_rn(v0, v1);
                if (gm0 + 8 < M)
                    *(__half2*)(outP + (size_t)(gm0 + 8) * 128 + nl) = __floats2half2_rn(v2, v3);
            } else {
                if (gm0 < M)
                    *(float2*)(outQ + (size_t)gm0 * 128 + nl) = make_float2(v0, v1);
                if (gm0 + 8 < M)
                    *(float2*)(outQ + (size_t)(gm0 + 8) * 128 + nl) = make_float2(v2, v3);
            }
        }
    }
#undef ISSUE
}

// ---------------------------------------------------------------
// launch — inputs: x, Wl1, bl1, Wr1, Wl2, bl2, Wr2, edge_index
// ---------------------------------------------------------------
extern "C" void kernel_launch(void* const* d_in, const int* in_sizes, int n_in,
                              void* d_out, int out_size) {
    const float* x   = (const float*)d_in[0];
    const float* Wl1 = (const float*)d_in[1];
    const float* bl1 = (const float*)d_in[2];
    const float* Wr1 = (const float*)d_in[3];
    const float* Wl2 = (const float*)d_in[4];
    const float* bl2 = (const float*)d_in[5];
    const float* Wr2 = (const float*)d_in[6];
    const void*  ei  = d_in[7];
    float* out = (float*)d_out;

    unsigned *A1hi, *A2hi, *A2lo;
    unsigned short *W1, *W2;
    float *b1, *b2, *q;
    __half* p;
    cudaGetSymbolAddress((void**)&A1hi, g_A1hi);
    cudaGetSymbolAddress((void**)&A2hi, g_A2hi);
    cudaGetSymbolAddress((void**)&A2lo, g_A2lo);
    cudaGetSymbolAddress((void**)&W1, g_W1);
    cudaGetSymbolAddress((void**)&W2, g_W2);
    cudaGetSymbolAddress((void**)&b1, g_b1);
    cudaGetSymbolAddress((void**)&b2, g_b2);
    cudaGetSymbolAddress((void**)&p, g_p);
    cudaGetSymbolAddress((void**)&q, g_q);

    // 0. init (degrees + format probe) + edge decode/degree count
    init_kernel<<<(N_NODES + 255) / 256, 256>>>((const int*)ei);
    convert_kernel<<<(2 * N_EDGES + 255) / 256, 256>>>(ei);

    // 1. CSR build (2-pass scan) + reorder
    scan_blocks_kernel<<<SCAN_NB, 256>>>();
    scan_finish_kernel<<<SCAN_NB, 256>>>();
    reorder_kernel<<<(N_EDGES + 255) / 256, 256>>>();

    // 2. fused prep: x fp16 (hi) + weights/biases
    {
        int items = XCONV_ITEMS + 2 * 256 * 256 + 512;
        prep_kernel<<<(items + 255) / 256, 256>>>(x, Wl1, Wr1, Wl2, Wr2, bl1, bl2);
    }

    // 3. layer-1 gather (fp16 x) -> A1 mean part
    gather1_kernel<<<(N_NODES + 7) / 8, 256>>>();

    // 4. GEMM1 (1 term): h = relu([mean|x]@[Wl1|Wr1]ᵀ + b1) -> A2 hi/lo
    {
        dim3 grid(2, GEMM_MB);
        gemm_mma_kernel<<<grid, 256>>>((const uint4*)A1hi, (const uint4*)A1hi,
                                       (const uint4*)W1, b1,
                                       nullptr, nullptr, A2hi, A2lo, N_NODES, 1);
    }

    // 5. GEMM2: p = hi(h)@Wl2ᵀ (fp16, 1 term), q = h@Wr2ᵀ + bl2 (fp32, 2 terms)
    {
        dim3 grid(2, GEMM_MB);
        gemm_mma_kernel<<<grid, 256>>>((const uint4*)A2hi, (const uint4*)A2lo,
                                       (const uint4*)W2, b2,
                                       p, q, nullptr, nullptr, N_NODES, 0);
    }

    // 6. layer-2 gather on fp16 p, fused with final combine
    gather2_kernel<<<(N_NODES + 7) / 8, 256>>>(out);
}

// round 13
// speedup vs baseline: 4.2092x; 1.1766x over previous
#include <cuda_runtime.h>
#include <cuda_fp16.h>
#include <cstdint>
#include <cstddef>

#define N_NODES 50000
#define N_EDGES 800000
#define SCAN_NB ((N_NODES + 255) / 256)   // 196 blocks
#define GEMM_MB ((N_NODES + 127) / 128)   // 391 CTAs in M
#define XCONV_ITEMS (N_NODES * 32)

// ---- device scratch ----
// A1: fp16 [M,256] packed as uints (row stride 128 uints)
// layout: uints 0..63 = mean part (128 fp16), uints 64..127 = x part
__device__ __align__(16) unsigned g_A1[(size_t)N_NODES * 128];
__device__ __align__(16) unsigned g_A2[(size_t)N_NODES * 128];   // h fp16
__device__ __align__(16) __half   g_p[(size_t)N_NODES * 128];    // p fp16
__device__ __align__(16) float    g_q[(size_t)N_NODES * 128];    // q fp32
__device__ __align__(16) unsigned short g_W1[256 * 256];         // fp16
__device__ __align__(16) unsigned short g_W2[256 * 256];         // fp16
__device__ __align__(16) float g_b1[256];
__device__ __align__(16) float g_b2[256];
__device__ __align__(16) float g_dinv[N_NODES];
__device__ __align__(16) int   g_degi[N_NODES];
__device__ __align__(16) int   g_row[N_NODES + 1];
__device__ __align__(16) int   g_cur[N_NODES];
__device__ __align__(16) int   g_csrc[N_EDGES];
__device__ __align__(16) int   g_bsum[SCAN_NB];
__device__ int g_fmt;

// ---------------- helpers ----------------
__device__ __forceinline__ unsigned su32(const void* p) {
    return (unsigned)__cvta_generic_to_shared(p);
}

__device__ __forceinline__ int eidx_at(const void* ei, int fmt, int i) {
    return fmt ? (int)((const long long*)ei)[i] : ((const int*)ei)[i];
}

// ---------------------------------------------------------------
// init: zero degrees + parallel edge-format probe (block 0)
// ---------------------------------------------------------------
__global__ void init_kernel(const int* __restrict__ ei32) {
    int i = blockIdx.x * blockDim.x + threadIdx.x;
    if (i < N_NODES) g_degi[i] = 0;
    if (blockIdx.x == 0) {
        __shared__ int s_nz;
        if (threadIdx.x == 0) s_nz = 0;
        __syncthreads();
        int nz = 0;
        for (int k = threadIdx.x; k < 512; k += 256)
            nz |= (ei32[2 * k + 1] != 0);
        if (nz) atomicOr(&s_nz, 1);
        __syncthreads();
        if (threadIdx.x == 0) g_fmt = s_nz ? 0 : 1;
    }
}

// degree count: decode dst half of edge_index directly
__global__ void deg_kernel(const void* __restrict__ ei) {
    int e = blockIdx.x * blockDim.x + threadIdx.x;
    if (e >= N_EDGES) return;
    int fmt = g_fmt;
    int d = eidx_at(ei, fmt, N_EDGES + e);
    atomicAdd(&g_degi[d], 1);
}

__global__ void scan_blocks_kernel() {
    __shared__ int s[256];
    int t = threadIdx.x;
    int i = blockIdx.x * 256 + t;
    int v = (i < N_NODES) ? g_degi[i] : 0;
    s[t] = v;
    __syncthreads();
#pragma unroll
    for (int off = 1; off < 256; off <<= 1) {
        int add = (t >= off) ? s[t - off] : 0;
        __syncthreads();
        s[t] += add;
        __syncthreads();
    }
    int incl = s[t];
    if (i < N_NODES) g_row[i] = incl - v;
    if (t == 255) g_bsum[blockIdx.x] = incl;
}

__global__ void scan_finish_kernel() {
    __shared__ int red[256];
    int t = threadIdx.x;
    int partial = 0;
    for (int k = t; k < blockIdx.x; k += 256) partial += g_bsum[k];
    red[t] = partial;
    __syncthreads();
#pragma unroll
    for (int s = 128; s > 0; s >>= 1) {
        if (t < s) red[t] += red[t + s];
        __syncthreads();
    }
    int boff = red[0];
    int i = blockIdx.x * 256 + t;
    if (i < N_NODES) {
        int r = g_row[i] + boff;
        g_row[i] = r;
        g_cur[i] = r;
        g_dinv[i] = 1.0f / fmaxf((float)g_degi[i], 1.0f);
    }
    if (i == 0) g_row[N_NODES] = N_EDGES;
}

// group edge sources by dst (decode straight from input)
__global__ void reorder_kernel(const void* __restrict__ ei) {
    int e = blockIdx.x * blockDim.x + threadIdx.x;
    if (e >= N_EDGES) return;
    int fmt = g_fmt;
    int s = eidx_at(ei, fmt, e);
    int d = eidx_at(ei, fmt, N_EDGES + e);
    int pos = atomicAdd(&g_cur[d], 1);
    g_csrc[pos] = s;
}

// ---------------------------------------------------------------
// prep: fused x fp16 conversion + weight/bias conversion
// ---------------------------------------------------------------
__global__ void prep_kernel(const float* __restrict__ x,
                            const float* __restrict__ Wl1, const float* __restrict__ Wr1,
                            const float* __restrict__ Wl2, const float* __restrict__ Wr2,
                            const float* __restrict__ bl1, const float* __restrict__ bl2) {
    int i = blockIdx.x * blockDim.x + threadIdx.x;
    if (i < XCONV_ITEMS) {
        int m = i >> 5, c4 = i & 31;
        float4 v = ((const float4*)x)[i];
        __half2 p0 = __floats2half2_rn(v.x, v.y);
        __half2 p1 = __floats2half2_rn(v.z, v.w);
        size_t base = (size_t)m * 128 + 64 + c4 * 2;
        g_A1[base]     = *reinterpret_cast<unsigned*>(&p0);
        g_A1[base + 1] = *reinterpret_cast<unsigned*>(&p1);
        return;
    }
    int j = i - XCONV_ITEMS;
    if (j < 2 * 256 * 256) {
        int op = j >> 16;
        int rem = j & 65535;
        int n = rem >> 8, k = rem & 255;
        float w;
        if (op == 0) w = (k < 128) ? Wl1[n * 128 + k] : Wr1[n * 128 + (k - 128)];
        else         w = (n < 128) ? Wl2[n * 256 + k] : Wr2[(n - 128) * 256 + k];
        __half hw = __float2half_rn(w);
        unsigned short hb = *reinterpret_cast<unsigned short*>(&hw);
        if (op == 0) g_W1[rem] = hb;
        else         g_W2[rem] = hb;
        return;
    }
    j -= 2 * 256 * 256;
    if (j < 256) g_b1[j] = bl1[j];
    else if (j < 512) {
        int n = j - 256;
        g_b2[n] = (n < 128) ? 0.0f : bl2[n - 128];
    }
}

// ---------------------------------------------------------------
// gather1: mean = (sum fp16 xh[neighbors]) * dinv -> A1 mean part
// ---------------------------------------------------------------
__global__ void gather1_kernel() {
    int warp = (blockIdx.x * blockDim.x + threadIdx.x) >> 5;
    int lane = threadIdx.x & 31;
    if (warp >= N_NODES) return;
    int start = g_row[warp];
    int end = g_row[warp + 1];
    float a0 = 0.f, a1 = 0.f, a2 = 0.f, a3 = 0.f;
    for (int base = start; base < end; base += 32) {
        int mye = base + lane;
        int sidx = (mye < end) ? g_csrc[mye] : 0;
        int cnt = end - base; if (cnt > 32) cnt = 32;
#pragma unroll 4
        for (int j = 0; j < cnt; j++) {
            int s = __shfl_sync(0xffffffffu, sidx, j);
            uint2 v = __ldg((const uint2*)(g_A1 + (size_t)s * 128 + 64) + lane);
            float2 f0 = __half22float2(*reinterpret_cast<__half2*>(&v.x));
            float2 f1 = __half22float2(*reinterpret_cast<__half2*>(&v.y));
            a0 += f0.x; a1 += f0.y; a2 += f1.x; a3 += f1.y;
        }
    }
    float sc = g_dinv[warp];
    __half2 p0 = __floats2half2_rn(a0 * sc, a1 * sc);
    __half2 p1 = __floats2half2_rn(a2 * sc, a3 * sc);
    size_t base = (size_t)warp * 128 + lane * 2;
    g_A1[base]     = *reinterpret_cast<unsigned*>(&p0);
    g_A1[base + 1] = *reinterpret_cast<unsigned*>(&p1);
}

// ---------------------------------------------------------------
// gather2 + final: out[n] = (sum fp16 p[nb]) * dinv[n] + q[n]
// ---------------------------------------------------------------
__global__ void gather2_kernel(float* __restrict__ out) {
    int warp = (blockIdx.x * blockDim.x + threadIdx.x) >> 5;
    int lane = threadIdx.x & 31;
    if (warp >= N_NODES) return;
    int start = g_row[warp];
    int end = g_row[warp + 1];
    float a0 = 0.f, a1 = 0.f, a2 = 0.f, a3 = 0.f;
    for (int base = start; base < end; base += 32) {
        int mye = base + lane;
        int sidx = (mye < end) ? g_csrc[mye] : 0;
        int cnt = end - base; if (cnt > 32) cnt = 32;
#pragma unroll 4
        for (int j = 0; j < cnt; j++) {
            int s = __shfl_sync(0xffffffffu, sidx, j);
            uint2 v = __ldg((const uint2*)(g_p + (size_t)s * 128) + lane);
            float2 f0 = __half22float2(*reinterpret_cast<__half2*>(&v.x));
            float2 f1 = __half22float2(*reinterpret_cast<__half2*>(&v.y));
            a0 += f0.x; a1 += f0.y; a2 += f1.x; a3 += f1.y;
        }
    }
    float s = g_dinv[warp];
    float4 q = __ldg((const float4*)(g_q + (size_t)warp * 128) + lane);
    float4 o;
    o.x = a0 * s + q.x;
    o.y = a1 * s + q.y;
    o.z = a2 * s + q.z;
    o.w = a3 * s + q.w;
    ((float4*)(out + (size_t)warp * 128))[lane] = o;
}

// ---------------------------------------------------------------
// mma.sync fp16 GEMM, 4-stage cp.async + ldmatrix. Single term, K=256.
// mode 1 (GEMM1): ReLU -> fp16 h (A2).
// mode 0 (GEMM2): p-CTA (n0=0) -> fp16 p; q-CTA (n0=128) -> fp32 q.
// ---------------------------------------------------------------
#define SSTR 40
#define NSTG 4
#define NCH 8

__global__ void __launch_bounds__(256, 2) gemm_mma_kernel(
    const uint4* __restrict__ A4, const uint4* __restrict__ W4,
    const float* __restrict__ bias,
    __half* __restrict__ outP, float* __restrict__ outQ,
    unsigned* __restrict__ outH,
    int M, int mode) {
    __shared__ __align__(16) unsigned short As[NSTG][128 * SSTR];
    __shared__ __align__(16) unsigned short Bs[NSTG][128 * SSTR];
    __shared__ float bsm[128];

    int tid = threadIdx.x;
    int wid = tid >> 5, lane = tid & 31;
    int wy = wid & 3, wx = wid >> 2;
    int tig = lane & 3, grp = lane >> 2;
    int m0 = blockIdx.y * 128;
    int n0 = blockIdx.x * 128;

    if (tid < 128) bsm[tid] = bias[n0 + tid];

    float acc[2][8][4];
#pragma unroll
    for (int a = 0; a < 2; a++)
#pragma unroll
        for (int b = 0; b < 8; b++)
#pragma unroll
            for (int c = 0; c < 4; c++) acc[a][b][c] = 0.f;

    int lrow = tid >> 1;
    int lc0 = (tid & 1) * 2;
    int gmA = m0 + lrow; if (gmA >= M) gmA = M - 1;
    size_t aRow = (size_t)gmA * 32;
    size_t bRow = (size_t)(n0 + lrow) * 32;

#define ISSUE(ss) do {                                                         \
        int kb_ = (ss);                                                        \
        unsigned da = su32(&As[(ss) & (NSTG - 1)][lrow * SSTR + lc0 * 8]);     \
        unsigned db = su32(&Bs[(ss) & (NSTG - 1)][lrow * SSTR + lc0 * 8]);     \
        const uint4* sa = &A4[aRow + kb_ * 4 + lc0];                           \
        const uint4* sb = &W4[bRow + kb_ * 4 + lc0];                           \
        asm volatile("cp.async.cg.shared.global [%0], [%1], 16;" :: "r"(da), "l"(sa)); \
        asm volatile("cp.async.cg.shared.global [%0], [%1], 16;" :: "r"(da + 16), "l"(sa + 1)); \
        asm volatile("cp.async.cg.shared.global [%0], [%1], 16;" :: "r"(db), "l"(sb)); \
        asm volatile("cp.async.cg.shared.global [%0], [%1], 16;" :: "r"(db + 16), "l"(sb + 1)); \
        asm volatile("cp.async.commit_group;");                                \
    } while (0)

    ISSUE(0); ISSUE(1); ISSUE(2);

    int arow = wy * 32 + (lane & 15);
    int acol = (lane >> 4);
    int brow = wx * 64 + ((lane >> 4) & 1) * 8 + (lane & 7);
    int bcol = (lane >> 3) & 1;

    for (int c = 0; c < NCH; c++) {
        if (c <= NCH - 3)      asm volatile("cp.async.wait_group 2;");
        else if (c == NCH - 2) asm volatile("cp.async.wait_group 1;");
        else                   asm volatile("cp.async.wait_group 0;");
        __syncthreads();
        if (c + 3 < NCH) ISSUE(c + 3);

        int b = c & (NSTG - 1);
        const unsigned short* As_ = As[b];
        const unsigned short* Bs_ = Bs[b];
#pragma unroll
        for (int ks = 0; ks < 2; ks++) {
            unsigned af[2][4];
#pragma unroll
            for (int mt = 0; mt < 2; mt++) {
                unsigned addr = su32(&As_[(arow + mt * 16) * SSTR + (ks * 2 + acol) * 8]);
                asm volatile(
                    "ldmatrix.sync.aligned.m8n8.x4.shared.b16 {%0,%1,%2,%3}, [%4];"
                    : "=r"(af[mt][0]), "=r"(af[mt][1]), "=r"(af[mt][2]), "=r"(af[mt][3])
                    : "r"(addr));
            }
#pragma unroll
            for (int g = 0; g < 4; g++) {
                unsigned bf[4];
                unsigned addr = su32(&Bs_[(brow + g * 16) * SSTR + (ks * 2 + bcol) * 8]);
                asm volatile(
                    "ldmatrix.sync.aligned.m8n8.x4.shared.b16 {%0,%1,%2,%3}, [%4];"
                    : "=r"(bf[0]), "=r"(bf[1]), "=r"(bf[2]), "=r"(bf[3])
                    : "r"(addr));
#pragma unroll
                for (int mt = 0; mt < 2; mt++) {
                    asm volatile(
                        "mma.sync.aligned.m16n8k16.row.col.f32.f16.f16.f32 "
                        "{%0,%1,%2,%3}, {%4,%5,%6,%7}, {%8,%9}, {%0,%1,%2,%3};"
                        : "+f"(acc[mt][2 * g][0]), "+f"(acc[mt][2 * g][1]),
                          "+f"(acc[mt][2 * g][2]), "+f"(acc[mt][2 * g][3])
                        : "r"(af[mt][0]), "r"(af[mt][1]),
                          "r"(af[mt][2]), "r"(af[mt][3]),
                          "r"(bf[0]), "r"(bf[1]));
                    asm volatile(
                        "mma.sync.aligned.m16n8k16.row.col.f32.f16.f16.f32 "
                        "{%0,%1,%2,%3}, {%4,%5,%6,%7}, {%8,%9}, {%0,%1,%2,%3};"
                        : "+f"(acc[mt][2 * g + 1][0]), "+f"(acc[mt][2 * g + 1][1]),
                          "+f"(acc[mt][2 * g + 1][2]), "+f"(acc[mt][2 * g + 1][3])
                        : "r"(af[mt][0]), "r"(af[mt][1]),
                          "r"(af[mt][2]), "r"(af[mt][3]),
                          "r"(bf[2]), "r"(bf[3]));
                }
            }
        }
    }

    // epilogue
#pragma unroll
    for (int mt = 0; mt < 2; mt++) {
        int gm0 = m0 + wy * 32 + mt * 16 + grp;
#pragma unroll
        for (int nt = 0; nt < 8; nt++) {
            int nl = wx * 64 + nt * 8 + tig * 2;
            float bx = bsm[nl], by = bsm[nl + 1];
            float v0 = acc[mt][nt][0] + bx;
            float v1 = acc[mt][nt][1] + by;
            float v2 = acc[mt][nt][2] + bx;
            float v3 = acc[mt][nt][3] + by;
            if (mode == 1) {
                v0 = fmaxf(v0, 0.f); v1 = fmaxf(v1, 0.f);
                v2 = fmaxf(v2, 0.f); v3 = fmaxf(v3, 0.f);
                __half2 h01 = __floats2half2_rn(v0, v1);
                __half2 h23 = __floats2half2_rn(v2, v3);
                if (gm0 < M)
                    outH[(size_t)gm0 * 128 + (nl >> 1) + n0 / 2] =
                        *reinterpret_cast<unsigned*>(&h01);
                if (gm0 + 8 < M)
                    outH[(size_t)(gm0 + 8) * 128 + (nl >> 1) + n0 / 2] =
                        *reinterpret_cast<unsigned*>(&h23);
            } else if (n0 == 0) {
                if (gm0 < M)
                    *(__half2*)(outP + (size_t)gm0 * 128 + nl) = __floats2half2_rn(v0, v1);
                if (gm0 + 8 < M)
                    *(__half2*)(outP + (size_t)(gm0 + 8) * 128 + nl) = __floats2half2_rn(v2, v3);
            } else {
                if (gm0 < M)
                    *(float2*)(outQ + (size_t)gm0 * 128 + nl) = make_float2(v0, v1);
                if (gm0 + 8 < M)
                    *(float2*)(outQ + (size_t)(gm0 + 8) * 128 + nl) = make_float2(v2, v3);
            }
        }
    }
#undef ISSUE
}

// ---------------------------------------------------------------
// launch — inputs: x, Wl1, bl1, Wr1, Wl2, bl2, Wr2, edge_index
// ---------------------------------------------------------------
extern "C" void kernel_launch(void* const* d_in, const int* in_sizes, int n_in,
                              void* d_out, int out_size) {
    const float* x   = (const float*)d_in[0];
    const float* Wl1 = (const float*)d_in[1];
    const float* bl1 = (const float*)d_in[2];
    const float* Wr1 = (const float*)d_in[3];
    const float* Wl2 = (const float*)d_in[4];
    const float* bl2 = (const float*)d_in[5];
    const float* Wr2 = (const float*)d_in[6];
    const void*  ei  = d_in[7];
    float* out = (float*)d_out;

    unsigned *A1, *A2;
    unsigned short *W1, *W2;
    float *b1, *b2, *q;
    __half* p;
    cudaGetSymbolAddress((void**)&A1, g_A1);
    cudaGetSymbolAddress((void**)&A2, g_A2);
    cudaGetSymbolAddress((void**)&W1, g_W1);
    cudaGetSymbolAddress((void**)&W2, g_W2);
    cudaGetSymbolAddress((void**)&b1, g_b1);
    cudaGetSymbolAddress((void**)&b2, g_b2);
    cudaGetSymbolAddress((void**)&p, g_p);
    cudaGetSymbolAddress((void**)&q, g_q);

    // 0. init (degree zero + format probe), then degree count
    init_kernel<<<(N_NODES + 255) / 256, 256>>>((const int*)ei);
    deg_kernel<<<(N_EDGES + 255) / 256, 256>>>(ei);

    // 1. CSR build (2-pass scan) + reorder (decodes from input directly)
    scan_blocks_kernel<<<SCAN_NB, 256>>>();
    scan_finish_kernel<<<SCAN_NB, 256>>>();
    reorder_kernel<<<(N_EDGES + 255) / 256, 256>>>(ei);

    // 2. fused prep: x fp16 + weights/biases
    {
        int items = XCONV_ITEMS + 2 * 256 * 256 + 512;
        prep_kernel<<<(items + 255) / 256, 256>>>(x, Wl1, Wr1, Wl2, Wr2, bl1, bl2);
    }

    // 3. layer-1 gather (fp16 x) -> A1 mean part
    gather1_kernel<<<(N_NODES + 7) / 8, 256>>>();

    // 4. GEMM1: h = relu([mean|x]@[Wl1|Wr1]ᵀ + b1) -> A2 fp16
    {
        dim3 grid(2, GEMM_MB);
        gemm_mma_kernel<<<grid, 256>>>((const uint4*)A1, (const uint4*)W1, b1,
                                       nullptr, nullptr, A2, N_NODES, 1);
    }

    // 5. GEMM2: p = h@Wl2ᵀ (fp16), q = h@Wr2ᵀ + bl2 (fp32)
    {
        dim3 grid(2, GEMM_MB);
        gemm_mma_kernel<<<grid, 256>>>((const uint4*)A2, (const uint4*)W2, b2,
                                       p, q, nullptr, N_NODES, 0);
    }

    // 6. layer-2 gather on fp16 p, fused with final combine
    gather2_kernel<<<(N_NODES + 7) / 8, 256>>>(out);
}